// round 2
// baseline (speedup 1.0000x reference)
#include <cuda_runtime.h>
#include <cuda_bf16.h>

typedef unsigned long long u64;

#define Bn   2
#define Sn   1024
#define Hn   768
#define Dn   24
#define HIDn 96

// ---------------- scratch (static device arrays; no allocation) ----------------
__device__ float g_Zj [Bn*Sn*Dn];
__device__ float g_Zi [Bn*Sn*Dn];
__device__ float g_Cj [Bn*Sn*HIDn];   // W_s1[:,0:24]  @ Zj       (per-j term)
__device__ float g_Ci [Bn*Sn*HIDn];   // W_s1[:,24:48] @ Zi + b1  (per-i term)
__device__ float g_P  [Bn*Sn*Sn];     // logits -> probs (in place)
__device__ float g_ctx[Bn*Sn*Hn];
__device__ float g_h1 [Bn*Sn*Hn];     // OUT_HID == 768

// ---------------- packed f32x2 helpers (sm_103a FFMA2 path) ----------------
__device__ __forceinline__ u64 pack2(float x, float y){
    u64 r;
    asm("mov.b64 %0, {%1, %2};" : "=l"(r)
        : "r"(__float_as_uint(x)), "r"(__float_as_uint(y)));
    return r;
}
__device__ __forceinline__ float2 unpack2(u64 v){
    unsigned lo, hi;
    asm("mov.b64 {%0, %1}, %2;" : "=r"(lo), "=r"(hi) : "l"(v));
    return make_float2(__uint_as_float(lo), __uint_as_float(hi));
}
__device__ __forceinline__ u64 fma2(u64 a, u64 b, u64 c){
    u64 d;
    asm("fma.rn.f32x2 %0, %1, %2, %3;" : "=l"(d) : "l"(a), "l"(b), "l"(c));
    return d;
}

// =================== kernel 1: projections + per-token MLP terms ===================
__global__ __launch_bounds__(256) void k_proj(
    const float* __restrict__ Hj, const float* __restrict__ Hi,
    const float* __restrict__ Wpj, const float* __restrict__ Wpi,
    const float* __restrict__ Ws1, const float* __restrict__ bs1)
{
    __shared__ float shj[Hn], shi[Hn], sz[48];
    const int row = blockIdx.x;            // b*S + s
    const int t = threadIdx.x;
    const float* hj = Hj + (size_t)row*Hn;
    const float* hi = Hi + (size_t)row*Hn;
    for (int k = t; k < Hn; k += 256){ shj[k] = hj[k]; shi[k] = hi[k]; }
    __syncthreads();

    if (t < 192){                           // 48 outputs x 4 partial lanes
        int o = t >> 2, part = t & 3;
        const float* w = (o < Dn) ? (Wpj + (size_t)o*Hn) : (Wpi + (size_t)(o - Dn)*Hn);
        const float* x = (o < Dn) ? shj : shi;
        float s = 0.f;
        for (int h = part; h < Hn; h += 4) s += w[h]*x[h];
        s += __shfl_xor_sync(0xffffffffu, s, 1);
        s += __shfl_xor_sync(0xffffffffu, s, 2);
        if (part == 0){
            sz[o] = s;
            if (o < Dn) g_Zj[(size_t)row*Dn + o]      = s;
            else        g_Zi[(size_t)row*Dn + (o-Dn)] = s;
        }
    }
    __syncthreads();

    if (t < 192){
        int h = (t < 96) ? t : t - 96;
        const float* wrow = Ws1 + h*96 + ((t < 96) ? 0 : 24);
        const float* z    = (t < 96) ? sz : (sz + 24);
        float s = (t < 96) ? 0.f : bs1[h];
        #pragma unroll
        for (int d = 0; d < 24; d++) s += wrow[d]*z[d];
        if (t < 96) g_Cj[(size_t)row*96 + h] = s;
        else        g_Ci[(size_t)row*96 + h] = s;
    }
}

// =================== kernel 2: pair MLP -> logits (the big one) ===================
// Block: 256 thr = 8 warps. Warp w owns j = j0+w; lane owns i = i0+lane.
// Each lane: 24 packed feature regs; per h: 12 LDS.128 of W pairs (broadcast) + 24 fma2.
__global__ __launch_bounds__(256,2) void k_pair(
    const float* __restrict__ Ws1, const float* __restrict__ Ws2,
    const float* __restrict__ bs2)
{
    __shared__ u64   whs[96][24];     // packed pairs of W_s1[:,48:96]
    __shared__ float ciT[96][33];
    __shared__ float cjs[8][96];
    __shared__ float ws2s[96];
    __shared__ float ziT[24][33];
    __shared__ float zjs[8][24];
    __shared__ float sbs2;

    const int t  = threadIdx.x;
    const int b  = blockIdx.z;
    const int i0 = blockIdx.x * 32;
    const int j0 = blockIdx.y * 8;
    const int base = b * Sn;

    for (int idx = t; idx < 96*24; idx += 256){
        int h = idx / 24, p = idx % 24;
        whs[h][p] = *(const u64*)(Ws1 + h*96 + 48 + 2*p);
    }
    if (t < 96) ws2s[t] = Ws2[t];
    if (t == 0) sbs2 = bs2[0];
    for (int idx = t; idx < 8*96; idx += 256){
        int jj = idx / 96, h = idx % 96;
        cjs[jj][h] = g_Cj[(size_t)(base + j0 + jj)*96 + h];
    }
    for (int idx = t; idx < 96*32; idx += 256){
        int l = idx / 96, h = idx % 96;
        ciT[h][l] = g_Ci[(size_t)(base + i0 + l)*96 + h];
    }
    for (int idx = t; idx < 24*32; idx += 256){
        int l = idx / 24, d = idx % 24;
        ziT[d][l] = g_Zi[(size_t)(base + i0 + l)*24 + d];
    }
    for (int idx = t; idx < 8*24; idx += 256){
        int jj = idx / 24, d = idx % 24;
        zjs[jj][d] = g_Zj[(size_t)(base + j0 + jj)*24 + d];
    }
    __syncthreads();

    const int wj = t >> 5, lane = t & 31;

    // per-pair features: f[0..11] = hadamard pairs, f[12..23] = absdiff pairs
    u64 f[24];
    #pragma unroll
    for (int p = 0; p < 12; p++){
        float zj0 = zjs[wj][2*p],     zj1 = zjs[wj][2*p+1];
        float zi0 = ziT[2*p][lane],   zi1 = ziT[2*p+1][lane];
        f[p]      = pack2(zj0*zi0, zj1*zi1);
        f[12 + p] = pack2(fabsf(zj0 - zi0), fabsf(zj1 - zi1));
    }

    float logit = sbs2;
    #pragma unroll 4
    for (int h = 0; h < 96; h++){
        u64 acc0 = pack2(ciT[h][lane], cjs[wj][h]);
        u64 acc1 = 0ull;
        #pragma unroll
        for (int p = 0; p < 24; p += 4){
            ulonglong2 w0 = *(const ulonglong2*)&whs[h][p];
            ulonglong2 w1 = *(const ulonglong2*)&whs[h][p+2];
            acc0 = fma2(w0.x, f[p],   acc0);
            acc1 = fma2(w0.y, f[p+1], acc1);
            acc0 = fma2(w1.x, f[p+2], acc0);
            acc1 = fma2(w1.y, f[p+3], acc1);
        }
        float2 a0 = unpack2(acc0), a1 = unpack2(acc1);
        float s = (a0.x + a1.x) + (a0.y + a1.y);
        s = fmaxf(s, 0.f);
        logit = fmaf(ws2s[h], s, logit);
    }
    g_P[(size_t)(base + j0 + wj)*Sn + i0 + lane] = logit;
}

// =================== kernel 3: masked softmax over i (in place) ===================
__global__ __launch_bounds__(256) void k_softmax(const float* __restrict__ mask){
    const int r = blockIdx.x;              // b*S + j
    const int b = r / Sn;
    float* row = g_P + (size_t)r*Sn;
    const float* mrow = mask + (size_t)b*Sn;
    const int t = threadIdx.x;
    __shared__ float red[256];

    float vals[4]; float mx = -3.402823466e38f;
    #pragma unroll
    for (int q = 0; q < 4; q++){
        int i = t + q*256;
        float v = row[i] + (1.0f - mrow[i]) * (-3.402823466e38f);
        vals[q] = v; mx = fmaxf(mx, v);
    }
    red[t] = mx; __syncthreads();
    for (int s = 128; s > 0; s >>= 1){ if (t < s) red[t] = fmaxf(red[t], red[t+s]); __syncthreads(); }
    mx = red[0]; __syncthreads();

    float sum = 0.f;
    #pragma unroll
    for (int q = 0; q < 4; q++){ vals[q] = __expf(vals[q] - mx); sum += vals[q]; }
    red[t] = sum; __syncthreads();
    for (int s = 128; s > 0; s >>= 1){ if (t < s) red[t] += red[t+s]; __syncthreads(); }
    float inv = 1.0f / red[0];
    #pragma unroll
    for (int q = 0; q < 4; q++) row[t + q*256] = vals[q] * inv;
}

// =================== kernel 4: ctx = P @ H_i  (NN GEMM, f32x2) ===================
// Tile M=64(j) x N=128(h) x K=16(i). 256 thr, thread tile 4x8 (4 fma2-cols).
__global__ __launch_bounds__(256) void k_ctx(const float* __restrict__ Hi){
    __shared__ u64   Asd[16][64];    // pack(a,a), [k][m]
    __shared__ float Bs [16][128];   // [k][n]
    const int t  = threadIdx.x;
    const int h0 = blockIdx.x * 128;
    const int j0 = blockIdx.y * 64;
    const int b  = blockIdx.z;
    const float* A  = g_P + (size_t)b*Sn*Sn;
    const float* Bm = Hi  + (size_t)b*Sn*Hn;

    const int tx = t & 15, ty = t >> 4;
    u64 acc[4][4];
    #pragma unroll
    for (int m = 0; m < 4; m++)
        #pragma unroll
        for (int n = 0; n < 4; n++) acc[m][n] = 0ull;

    for (int k0 = 0; k0 < Sn; k0 += 16){
        {   // A tile: 64 m x 16 k, transposed + duplicated
            int m = t >> 2, kq = t & 3;
            float4 av = *(const float4*)&A[(size_t)(j0 + m)*Sn + k0 + kq*4];
            Asd[kq*4+0][m] = pack2(av.x, av.x);
            Asd[kq*4+1][m] = pack2(av.y, av.y);
            Asd[kq*4+2][m] = pack2(av.z, av.z);
            Asd[kq*4+3][m] = pack2(av.w, av.w);
        }
        {   // B tile: 16 k x 128 h
            int r = t >> 4, c8 = (t & 15) * 8;
            const float* src = &Bm[(size_t)(k0 + r)*Hn + h0 + c8];
            *(float4*)&Bs[r][c8]     = *(const float4*)src;
            *(float4*)&Bs[r][c8 + 4] = *(const float4*)(src + 4);
        }
        __syncthreads();
        #pragma unroll
        for (int k = 0; k < 16; k++){
            ulonglong2 a01 = *(const ulonglong2*)&Asd[k][ty*4];
            ulonglong2 a23 = *(const ulonglong2*)&Asd[k][ty*4 + 2];
            ulonglong2 b01 = *(const ulonglong2*)&Bs[k][tx*8];
            ulonglong2 b23 = *(const ulonglong2*)&Bs[k][tx*8 + 4];
            u64 av[4] = {a01.x, a01.y, a23.x, a23.y};
            u64 bv[4] = {b01.x, b01.y, b23.x, b23.y};
            #pragma unroll
            for (int m = 0; m < 4; m++)
                #pragma unroll
                for (int n = 0; n < 4; n++)
                    acc[m][n] = fma2(av[m], bv[n], acc[m][n]);
        }
        __syncthreads();
    }
    #pragma unroll
    for (int m = 0; m < 4; m++){
        float out[8];
        #pragma unroll
        for (int n = 0; n < 4; n++){ float2 v = unpack2(acc[m][n]); out[2*n] = v.x; out[2*n+1] = v.y; }
        float* dst = &g_ctx[(size_t)(b*Sn + j0 + ty*4 + m)*Hn + h0 + tx*8];
        *(float4*)dst       = *(float4*)&out[0];
        *(float4*)(dst + 4) = *(float4*)&out[4];
    }
}

// =================== kernel 5/6: val-MLP GEMMs (NT, f32x2) ===================
// MODE 0: h1 = relu([ctx,Hj,ctx*Hj] @ Wv1^T + b1)   (K=2304, virtual A)
// MODE 1: out = alpha*(h1 @ Wv2^T + b2)             (K=768)
template<int MODE>
__global__ __launch_bounds__(256) void k_nt(
    const float* __restrict__ Aext,      // MODE0: Hj; MODE1: unused
    const float* __restrict__ W,         // [N, K] row-major (K contiguous)
    const float* __restrict__ bias,
    const float* __restrict__ alpha_p,
    float* __restrict__ Cout,            // MODE1 output (d_out); MODE0 writes g_h1
    int K)
{
    __shared__ u64   Asd[16][64];
    __shared__ float Bs [16][128];
    const int t  = threadIdx.x;
    const int n0 = blockIdx.x * 128;
    const int m0 = blockIdx.y * 64;
    const int tx = t & 15, ty = t >> 4;

    u64 acc[4][4];
    #pragma unroll
    for (int m = 0; m < 4; m++)
        #pragma unroll
        for (int n = 0; n < 4; n++) acc[m][n] = 0ull;

    for (int k0 = 0; k0 < K; k0 += 16){
        {   // A tile
            int m = t >> 2, kq = t & 3;
            int s = m0 + m;
            float4 av;
            if (MODE == 0){
                int fo = k0 + kq*4;
                if (fo < 768){
                    av = *(const float4*)&g_ctx[(size_t)s*768 + fo];
                } else if (fo < 1536){
                    av = *(const float4*)&Aext[(size_t)s*768 + fo - 768];
                } else {
                    float4 c  = *(const float4*)&g_ctx[(size_t)s*768 + fo - 1536];
                    float4 hj = *(const float4*)&Aext [(size_t)s*768 + fo - 1536];
                    av = make_float4(c.x*hj.x, c.y*hj.y, c.z*hj.z, c.w*hj.w);
                }
            } else {
                av = *(const float4*)&g_h1[(size_t)s*768 + k0 + kq*4];
            }
            Asd[kq*4+0][m] = pack2(av.x, av.x);
            Asd[kq*4+1][m] = pack2(av.y, av.y);
            Asd[kq*4+2][m] = pack2(av.z, av.z);
            Asd[kq*4+3][m] = pack2(av.w, av.w);
        }
        {   // W tile: Bs[k][n] = W[(n0+n)*K + k0+k]
            int n = t & 127, kh = t >> 7;       // kh in {0,1}
            const float* wsrc = &W[(size_t)(n0 + n)*K + k0 + kh*8];
            float4 w0 = *(const float4*)wsrc;
            float4 w1 = *(const float4*)(wsrc + 4);
            Bs[kh*8+0][n] = w0.x; Bs[kh*8+1][n] = w0.y;
            Bs[kh*8+2][n] = w0.z; Bs[kh*8+3][n] = w0.w;
            Bs[kh*8+4][n] = w1.x; Bs[kh*8+5][n] = w1.y;
            Bs[kh*8+6][n] = w1.z; Bs[kh*8+7][n] = w1.w;
        }
        __syncthreads();
        #pragma unroll
        for (int k = 0; k < 16; k++){
            ulonglong2 a01 = *(const ulonglong2*)&Asd[k][ty*4];
            ulonglong2 a23 = *(const ulonglong2*)&Asd[k][ty*4 + 2];
            ulonglong2 b01 = *(const ulonglong2*)&Bs[k][tx*8];
            ulonglong2 b23 = *(const ulonglong2*)&Bs[k][tx*8 + 4];
            u64 av[4] = {a01.x, a01.y, a23.x, a23.y};
            u64 bv[4] = {b01.x, b01.y, b23.x, b23.y};
            #pragma unroll
            for (int m = 0; m < 4; m++)
                #pragma unroll
                for (int n = 0; n < 4; n++)
                    acc[m][n] = fma2(av[m], bv[n], acc[m][n]);
        }
        __syncthreads();
    }

    float alpha = (MODE == 1) ? alpha_p[0] : 1.0f;
    #pragma unroll
    for (int m = 0; m < 4; m++){
        float out[8];
        #pragma unroll
        for (int n = 0; n < 4; n++){ float2 v = unpack2(acc[m][n]); out[2*n] = v.x; out[2*n+1] = v.y; }
        int nbase = n0 + tx*8;
        #pragma unroll
        for (int q = 0; q < 8; q++){
            float v = out[q] + bias[nbase + q];
            out[q] = (MODE == 0) ? fmaxf(v, 0.f) : v * alpha;
        }
        float* dst = (MODE == 0)
            ? &g_h1[(size_t)(m0 + ty*4 + m)*768 + nbase]
            : &Cout[(size_t)(m0 + ty*4 + m)*768 + nbase];
        *(float4*)dst       = *(float4*)&out[0];
        *(float4*)(dst + 4) = *(float4*)&out[4];
    }
}

// =============================== launch ===============================
extern "C" void kernel_launch(void* const* d_in, const int* in_sizes, int n_in,
                              void* d_out, int out_size)
{
    const float* Hj    = (const float*)d_in[0];
    const float* Hi    = (const float*)d_in[1];
    const float* mask  = (const float*)d_in[2];
    const float* Wpj   = (const float*)d_in[3];
    const float* Wpi   = (const float*)d_in[4];
    const float* Ws1   = (const float*)d_in[5];
    const float* bs1   = (const float*)d_in[6];
    const float* Ws2   = (const float*)d_in[7];
    const float* bs2   = (const float*)d_in[8];
    const float* Wv1   = (const float*)d_in[9];
    const float* bv1   = (const float*)d_in[10];
    const float* Wv2   = (const float*)d_in[11];
    const float* bv2   = (const float*)d_in[12];
    const float* alpha = (const float*)d_in[13];
    float* out = (float*)d_out;

    k_proj<<<Bn*Sn, 256>>>(Hj, Hi, Wpj, Wpi, Ws1, bs1);

    dim3 gp(Sn/32, Sn/8, Bn);
    k_pair<<<gp, 256>>>(Ws1, Ws2, bs2);

    k_softmax<<<Bn*Sn, 256>>>(mask);

    dim3 gc(Hn/128, Sn/64, Bn);
    k_ctx<<<gc, 256>>>(Hi);

    dim3 gv(768/128, (Bn*Sn)/64);
    k_nt<0><<<gv, 256>>>(Hj, Wv1, bv1, alpha, out, 2304);
    k_nt<1><<<gv, 256>>>(Hj, Wv2, bv2, alpha, out, 768);
}

// round 3
// speedup vs baseline: 1.2049x; 1.2049x over previous
#include <cuda_runtime.h>
#include <cuda_bf16.h>

typedef unsigned long long u64;

#define Bn   2
#define Sn   1024
#define Hn   768
#define Dn   24
#define HIDn 96

// ---------------- scratch (static device arrays; no allocation) ----------------
__device__ float g_Zj [Bn*Sn*Dn];
__device__ float g_Zi [Bn*Sn*Dn];
__device__ float g_Cj [Bn*Sn*HIDn];   // W_s1[:,0:24]  @ Zj       (per-j term)
__device__ float g_Ci [Bn*Sn*HIDn];   // W_s1[:,24:48] @ Zi + b1  (per-i term)
__device__ float g_P  [Bn*Sn*Sn];     // logits -> probs (in place)
__device__ float g_ctx[Bn*Sn*Hn];
__device__ float g_h1 [Bn*Sn*Hn];     // OUT_HID == 768

// ---------------- packed f32x2 helpers (sm_103a FFMA2 path) ----------------
__device__ __forceinline__ u64 pack2(float x, float y){
    u64 r;
    asm("mov.b64 %0, {%1, %2};" : "=l"(r)
        : "r"(__float_as_uint(x)), "r"(__float_as_uint(y)));
    return r;
}
__device__ __forceinline__ float2 unpack2(u64 v){
    unsigned lo, hi;
    asm("mov.b64 {%0, %1}, %2;" : "=r"(lo), "=r"(hi) : "l"(v));
    return make_float2(__uint_as_float(lo), __uint_as_float(hi));
}
__device__ __forceinline__ u64 fma2(u64 a, u64 b, u64 c){
    u64 d;
    asm("fma.rn.f32x2 %0, %1, %2, %3;" : "=l"(d) : "l"(a), "l"(b), "l"(c));
    return d;
}
__device__ __forceinline__ u64 add2(u64 a, u64 b){
    u64 d;
    asm("add.rn.f32x2 %0, %1, %2;" : "=l"(d) : "l"(a), "l"(b));
    return d;
}

// =================== kernel 1: projections + per-token MLP terms ===================
__global__ __launch_bounds__(256) void k_proj(
    const float* __restrict__ Hj, const float* __restrict__ Hi,
    const float* __restrict__ Wpj, const float* __restrict__ Wpi,
    const float* __restrict__ Ws1, const float* __restrict__ bs1)
{
    __shared__ float shj[Hn], shi[Hn];
    __shared__ float sz[48];
    __shared__ float sws1[96][97];
    const int row = blockIdx.x;
    const int t = threadIdx.x;
    const float* hj = Hj + (size_t)row*Hn;
    const float* hi = Hi + (size_t)row*Hn;
    for (int k = t; k < Hn; k += 256){ shj[k] = hj[k]; shi[k] = hi[k]; }
    for (int idx = t; idx < 96*96; idx += 256) sws1[idx/96][idx%96] = Ws1[idx];
    __syncthreads();

    const int w = t >> 5, lane = t & 31;
    for (int o = w; o < 48; o += 8){
        const float* wv = (o < 24) ? (Wpj + (size_t)o*Hn) : (Wpi + (size_t)(o-24)*Hn);
        const float* x  = (o < 24) ? shj : shi;
        float s0 = 0.f, s1 = 0.f;
        #pragma unroll
        for (int h = lane; h < Hn; h += 64){
            s0 = fmaf(wv[h],    x[h],    s0);
            s1 = fmaf(wv[h+32], x[h+32], s1);
        }
        float s = s0 + s1;
        #pragma unroll
        for (int off = 16; off; off >>= 1) s += __shfl_xor_sync(0xffffffffu, s, off);
        if (lane == 0){
            sz[o] = s;
            if (o < 24) g_Zj[(size_t)row*24 + o]      = s;
            else        g_Zi[(size_t)row*24 + (o-24)] = s;
        }
    }
    __syncthreads();

    if (t < 192){
        int h = (t < 96) ? t : t - 96;
        const float* z  = (t < 96) ? sz : (sz + 24);
        const float* wr = &sws1[h][(t < 96) ? 0 : 24];
        float s = (t < 96) ? 0.f : bs1[h];
        #pragma unroll
        for (int d = 0; d < 24; d++) s = fmaf(wr[d], z[d], s);
        if (t < 96) g_Cj[(size_t)row*96 + h] = s;
        else        g_Ci[(size_t)row*96 + h] = s;
    }
}

// =================== kernel 2: pair MLP -> logits ===================
__global__ __launch_bounds__(256) void k_pair(
    const float* __restrict__ Ws1, const float* __restrict__ Ws2,
    const float* __restrict__ bs2)
{
    __shared__ __align__(16) u64 whs[96][24];   // packed pairs of W_s1[:,48:96]
    __shared__ float ciT[96][33];
    __shared__ float cjs[8][96];
    __shared__ float ws2s[96];
    __shared__ float ziT[24][33];
    __shared__ float zjs[8][24];
    __shared__ float sbs2;

    const int t  = threadIdx.x;
    const int b  = blockIdx.z;
    const int i0 = blockIdx.x * 32;
    const int j0 = blockIdx.y * 8;
    const int base = b * Sn;

    for (int idx = t; idx < 96*24; idx += 256){
        int h = idx / 24, p = idx % 24;
        whs[h][p] = *(const u64*)(Ws1 + h*96 + 48 + 2*p);
    }
    if (t < 96) ws2s[t] = Ws2[t];
    if (t == 0) sbs2 = bs2[0];
    for (int idx = t; idx < 8*96; idx += 256){
        int jj = idx / 96, h = idx % 96;
        cjs[jj][h] = g_Cj[(size_t)(base + j0 + jj)*96 + h];
    }
    for (int idx = t; idx < 96*32; idx += 256){
        int l = idx / 96, h = idx % 96;
        ciT[h][l] = g_Ci[(size_t)(base + i0 + l)*96 + h];
    }
    for (int idx = t; idx < 24*32; idx += 256){
        int l = idx / 24, d = idx % 24;
        ziT[d][l] = g_Zi[(size_t)(base + i0 + l)*24 + d];
    }
    for (int idx = t; idx < 8*24; idx += 256){
        int jj = idx / 24, d = idx % 24;
        zjs[jj][d] = g_Zj[(size_t)(base + j0 + jj)*24 + d];
    }
    __syncthreads();

    const int wj = t >> 5, lane = t & 31;

    u64 f[24];
    #pragma unroll
    for (int p = 0; p < 12; p++){
        float zj0 = zjs[wj][2*p],   zj1 = zjs[wj][2*p+1];
        float zi0 = ziT[2*p][lane], zi1 = ziT[2*p+1][lane];
        f[p]      = pack2(zj0*zi0, zj1*zi1);
        f[12 + p] = pack2(fabsf(zj0 - zi0), fabsf(zj1 - zi1));
    }

    float logit = sbs2;
    #pragma unroll 2
    for (int h = 0; h < 96; h++){
        u64 acc0 = pack2(ciT[h][lane], cjs[wj][h]);
        u64 acc1 = 0ull, acc2 = 0ull, acc3 = 0ull;
        #pragma unroll
        for (int p = 0; p < 24; p += 4){
            ulonglong2 w0 = *(const ulonglong2*)&whs[h][p];
            ulonglong2 w1 = *(const ulonglong2*)&whs[h][p+2];
            acc0 = fma2(w0.x, f[p],   acc0);
            acc1 = fma2(w0.y, f[p+1], acc1);
            acc2 = fma2(w1.x, f[p+2], acc2);
            acc3 = fma2(w1.y, f[p+3], acc3);
        }
        u64 s2 = add2(add2(acc0, acc1), add2(acc2, acc3));
        float2 sv = unpack2(s2);
        float s = fmaxf(sv.x + sv.y, 0.f);
        logit = fmaf(ws2s[h], s, logit);
    }
    g_P[(size_t)(base + j0 + wj)*Sn + i0 + lane] = logit;
}

// =================== kernel 3: masked softmax over i (in place) ===================
__global__ __launch_bounds__(256) void k_softmax(const float* __restrict__ mask){
    const int r = blockIdx.x;
    const int b = r / Sn;
    float* row = g_P + (size_t)r*Sn;
    const float* mrow = mask + (size_t)b*Sn;
    const int t = threadIdx.x;
    __shared__ float red[256];

    float vals[4]; float mx = -3.402823466e38f;
    #pragma unroll
    for (int q = 0; q < 4; q++){
        int i = t + q*256;
        float v = row[i] + (1.0f - mrow[i]) * (-3.402823466e38f);
        vals[q] = v; mx = fmaxf(mx, v);
    }
    red[t] = mx; __syncthreads();
    for (int s = 128; s > 0; s >>= 1){ if (t < s) red[t] = fmaxf(red[t], red[t+s]); __syncthreads(); }
    mx = red[0]; __syncthreads();

    float sum = 0.f;
    #pragma unroll
    for (int q = 0; q < 4; q++){ vals[q] = __expf(vals[q] - mx); sum += vals[q]; }
    red[t] = sum; __syncthreads();
    for (int s = 128; s > 0; s >>= 1){ if (t < s) red[t] += red[t+s]; __syncthreads(); }
    float inv = 1.0f / red[0];
    #pragma unroll
    for (int q = 0; q < 4; q++) row[t + q*256] = vals[q] * inv;
}

// =================== unified double-buffered GEMM (f32x2) ===================
// MODE 0: ctx = P @ Hi                  (NN, K=1024, per-batch)
// MODE 1: h1  = relu([ctx,Hj,ctx*Hj] @ Wv1^T + b)   (NT, K=2304, virtual A)
// MODE 2: out = alpha*(h1 @ Wv2^T + b)              (NT, K=768)
// 128 threads, tile M=64 x N=64 x K=16, double-buffered, thread tile 4x8.
template<int MODE>
__global__ __launch_bounds__(128) void k_gemm(
    const float* __restrict__ BW,      // MODE0: Hi; MODE1: Wv1; MODE2: Wv2
    const float* __restrict__ Hj,      // MODE1 only
    const float* __restrict__ bias,    // MODE1/2
    const float* __restrict__ alpha_p, // MODE2
    float* __restrict__ Cout)          // MODE2 output
{
    constexpr int K = (MODE == 0) ? 1024 : (MODE == 1) ? 2304 : 768;
    constexpr int T = K / 16;
    __shared__ __align__(16) u64   As[2][16][64];
    __shared__ __align__(16) float Bs[2][16][64];

    const int t  = threadIdx.x;
    const int n0 = blockIdx.x * 64;
    const int m0 = blockIdx.y * 64;
    const int b  = (MODE == 0) ? blockIdx.z : 0;
    const int rowbase = (MODE == 0) ? b*Sn + m0 : m0;

    const int am = t >> 1, ak8 = (t & 1) * 8;       // A staging
    const int bk = t >> 3, bn8 = (t & 7) * 8;       // B staging (NN)
    const int bn = t >> 1, bk8 = (t & 1) * 8;       // B staging (NT)
    const int ty4 = (t >> 3) * 4, tx8 = (t & 7) * 8;

    const float* ArowP = g_P  + (size_t)(rowbase + am)*Sn;
    const float* ArowC = g_ctx + (size_t)(rowbase + am)*Hn;
    const float* ArowH = (MODE == 1) ? (Hj + (size_t)(rowbase + am)*Hn) : (const float*)0;
    const float* ArowH1 = g_h1 + (size_t)(rowbase + am)*Hn;
    const float* Bsrc = (MODE == 0) ? (BW + (size_t)b*Sn*Hn) : BW;

    float4 a0, a1, b0, b1;

    auto ldg = [&](int k0){
        const int fo = k0 + ak8;
        if (MODE == 0){
            a0 = *(const float4*)(ArowP + fo); a1 = *(const float4*)(ArowP + fo + 4);
        } else if (MODE == 2){
            a0 = *(const float4*)(ArowH1 + fo); a1 = *(const float4*)(ArowH1 + fo + 4);
        } else {
            if (fo < 768){
                a0 = *(const float4*)(ArowC + fo); a1 = *(const float4*)(ArowC + fo + 4);
            } else if (fo < 1536){
                a0 = *(const float4*)(ArowH + fo - 768); a1 = *(const float4*)(ArowH + fo - 764);
            } else {
                float4 c0 = *(const float4*)(ArowC + fo - 1536);
                float4 c1 = *(const float4*)(ArowC + fo - 1532);
                float4 h0 = *(const float4*)(ArowH + fo - 1536);
                float4 h1v = *(const float4*)(ArowH + fo - 1532);
                a0 = make_float4(c0.x*h0.x, c0.y*h0.y, c0.z*h0.z, c0.w*h0.w);
                a1 = make_float4(c1.x*h1v.x, c1.y*h1v.y, c1.z*h1v.z, c1.w*h1v.w);
            }
        }
        if (MODE == 0){
            const float* s = Bsrc + (size_t)(k0 + bk)*Hn + n0 + bn8;
            b0 = *(const float4*)s; b1 = *(const float4*)(s + 4);
        } else {
            const float* s = Bsrc + (size_t)(n0 + bn)*K + k0 + bk8;
            b0 = *(const float4*)s; b1 = *(const float4*)(s + 4);
        }
    };
    auto sts = [&](int buf){
        As[buf][ak8+0][am] = pack2(a0.x, a0.x);
        As[buf][ak8+1][am] = pack2(a0.y, a0.y);
        As[buf][ak8+2][am] = pack2(a0.z, a0.z);
        As[buf][ak8+3][am] = pack2(a0.w, a0.w);
        As[buf][ak8+4][am] = pack2(a1.x, a1.x);
        As[buf][ak8+5][am] = pack2(a1.y, a1.y);
        As[buf][ak8+6][am] = pack2(a1.z, a1.z);
        As[buf][ak8+7][am] = pack2(a1.w, a1.w);
        if (MODE == 0){
            *(float4*)&Bs[buf][bk][bn8]     = b0;
            *(float4*)&Bs[buf][bk][bn8 + 4] = b1;
        } else {
            Bs[buf][bk8+0][bn] = b0.x; Bs[buf][bk8+1][bn] = b0.y;
            Bs[buf][bk8+2][bn] = b0.z; Bs[buf][bk8+3][bn] = b0.w;
            Bs[buf][bk8+4][bn] = b1.x; Bs[buf][bk8+5][bn] = b1.y;
            Bs[buf][bk8+6][bn] = b1.z; Bs[buf][bk8+7][bn] = b1.w;
        }
    };

    u64 acc[4][4];
    #pragma unroll
    for (int m = 0; m < 4; m++)
        #pragma unroll
        for (int n = 0; n < 4; n++) acc[m][n] = 0ull;

    ldg(0); sts(0); __syncthreads();

    for (int tt = 0; tt < T; tt++){
        const int cur = tt & 1;
        if (tt + 1 < T) ldg((tt + 1) * 16);
        #pragma unroll
        for (int k = 0; k < 16; k++){
            ulonglong2 A01 = *(const ulonglong2*)&As[cur][k][ty4];
            ulonglong2 A23 = *(const ulonglong2*)&As[cur][k][ty4 + 2];
            ulonglong2 B01 = *(const ulonglong2*)&Bs[cur][k][tx8];
            ulonglong2 B23 = *(const ulonglong2*)&Bs[cur][k][tx8 + 4];
            u64 av[4] = {A01.x, A01.y, A23.x, A23.y};
            u64 bv[4] = {B01.x, B01.y, B23.x, B23.y};
            #pragma unroll
            for (int m = 0; m < 4; m++)
                #pragma unroll
                for (int n = 0; n < 4; n++)
                    acc[m][n] = fma2(av[m], bv[n], acc[m][n]);
        }
        if (tt + 1 < T) sts(cur ^ 1);
        __syncthreads();
    }

    const float alpha = (MODE == 2) ? alpha_p[0] : 1.0f;
    #pragma unroll
    for (int m = 0; m < 4; m++){
        float out[8];
        #pragma unroll
        for (int n = 0; n < 4; n++){
            float2 v = unpack2(acc[m][n]);
            out[2*n] = v.x; out[2*n+1] = v.y;
        }
        const int nbase = n0 + tx8;
        if (MODE != 0){
            #pragma unroll
            for (int q = 0; q < 8; q++){
                float v = out[q] + bias[nbase + q];
                out[q] = (MODE == 1) ? fmaxf(v, 0.f) : v * alpha;
            }
        }
        float* dst;
        if      (MODE == 0) dst = &g_ctx[(size_t)(rowbase + ty4 + m)*Hn + nbase];
        else if (MODE == 1) dst = &g_h1 [(size_t)(rowbase + ty4 + m)*Hn + nbase];
        else                dst = &Cout [(size_t)(rowbase + ty4 + m)*Hn + nbase];
        *(float4*)dst       = *(float4*)&out[0];
        *(float4*)(dst + 4) = *(float4*)&out[4];
    }
}

// =============================== launch ===============================
extern "C" void kernel_launch(void* const* d_in, const int* in_sizes, int n_in,
                              void* d_out, int out_size)
{
    const float* Hj    = (const float*)d_in[0];
    const float* Hi    = (const float*)d_in[1];
    const float* mask  = (const float*)d_in[2];
    const float* Wpj   = (const float*)d_in[3];
    const float* Wpi   = (const float*)d_in[4];
    const float* Ws1   = (const float*)d_in[5];
    const float* bs1   = (const float*)d_in[6];
    const float* Ws2   = (const float*)d_in[7];
    const float* bs2   = (const float*)d_in[8];
    const float* Wv1   = (const float*)d_in[9];
    const float* bv1   = (const float*)d_in[10];
    const float* Wv2   = (const float*)d_in[11];
    const float* bv2   = (const float*)d_in[12];
    const float* alpha = (const float*)d_in[13];
    float* out = (float*)d_out;

    k_proj<<<Bn*Sn, 256>>>(Hj, Hi, Wpj, Wpi, Ws1, bs1);

    dim3 gp(Sn/32, Sn/8, Bn);
    k_pair<<<gp, 256>>>(Ws1, Ws2, bs2);

    k_softmax<<<Bn*Sn, 256>>>(mask);

    dim3 gc(Hn/64, Sn/64, Bn);
    k_gemm<0><<<gc, 128>>>(Hi, nullptr, nullptr, nullptr, nullptr);

    dim3 gv(Hn/64, (Bn*Sn)/64, 1);
    k_gemm<1><<<gv, 128>>>(Wv1, Hj, bv1, nullptr, nullptr);
    k_gemm<2><<<gv, 128>>>(Wv2, nullptr, bv2, alpha, out);
}

// round 4
// speedup vs baseline: 1.3241x; 1.0990x over previous
#include <cuda_runtime.h>
#include <cuda_bf16.h>

typedef unsigned long long u64;

#define Bn   2
#define Sn   1024
#define Hn   768
#define Dn   24
#define HIDn 96

// ---------------- scratch (static device arrays; no allocation) ----------------
__device__ float g_Zj [Bn*Sn*Dn];
__device__ float g_Zi [Bn*Sn*Dn];
__device__ float g_Cj [Bn*Sn*HIDn];   // W_s1[:,0:24]  @ Zj       (per-j term)
__device__ float g_Ci [Bn*Sn*HIDn];   // W_s1[:,24:48] @ Zi + b1  (per-i term)
__device__ float g_P  [Bn*Sn*Sn];     // logits -> probs (in place)
__device__ float g_ctx[Bn*Sn*Hn];
__device__ float g_h1 [Bn*Sn*Hn];     // OUT_HID == 768

// ---------------- packed f32x2 helpers (sm_103a FFMA2 path) ----------------
__device__ __forceinline__ u64 pack2(float x, float y){
    u64 r;
    asm("mov.b64 %0, {%1, %2};" : "=l"(r)
        : "r"(__float_as_uint(x)), "r"(__float_as_uint(y)));
    return r;
}
__device__ __forceinline__ float2 unpack2(u64 v){
    unsigned lo, hi;
    asm("mov.b64 {%0, %1}, %2;" : "=r"(lo), "=r"(hi) : "l"(v));
    return make_float2(__uint_as_float(lo), __uint_as_float(hi));
}
__device__ __forceinline__ u64 fma2(u64 a, u64 b, u64 c){
    u64 d;
    asm("fma.rn.f32x2 %0, %1, %2, %3;" : "=l"(d) : "l"(a), "l"(b), "l"(c));
    return d;
}
__device__ __forceinline__ u64 add2(u64 a, u64 b){
    u64 d;
    asm("add.rn.f32x2 %0, %1, %2;" : "=l"(d) : "l"(a), "l"(b));
    return d;
}

// =================== kernel 1: projections + per-token MLP terms ===================
__global__ __launch_bounds__(256) void k_proj(
    const float* __restrict__ Hj, const float* __restrict__ Hi,
    const float* __restrict__ Wpj, const float* __restrict__ Wpi,
    const float* __restrict__ Ws1, const float* __restrict__ bs1)
{
    __shared__ float shj[Hn], shi[Hn];
    __shared__ float sz[48];
    __shared__ float sws1[96][97];
    const int row = blockIdx.x;
    const int t = threadIdx.x;
    const float* hj = Hj + (size_t)row*Hn;
    const float* hi = Hi + (size_t)row*Hn;
    for (int k = t; k < Hn; k += 256){ shj[k] = hj[k]; shi[k] = hi[k]; }
    for (int idx = t; idx < 96*96; idx += 256) sws1[idx/96][idx%96] = Ws1[idx];
    __syncthreads();

    const int w = t >> 5, lane = t & 31;
    for (int o = w; o < 48; o += 8){
        const float* wv = (o < 24) ? (Wpj + (size_t)o*Hn) : (Wpi + (size_t)(o-24)*Hn);
        const float* x  = (o < 24) ? shj : shi;
        float s0 = 0.f, s1 = 0.f;
        #pragma unroll
        for (int h = lane; h < Hn; h += 64){
            s0 = fmaf(wv[h],    x[h],    s0);
            s1 = fmaf(wv[h+32], x[h+32], s1);
        }
        float s = s0 + s1;
        #pragma unroll
        for (int off = 16; off; off >>= 1) s += __shfl_xor_sync(0xffffffffu, s, off);
        if (lane == 0){
            sz[o] = s;
            if (o < 24) g_Zj[(size_t)row*24 + o]      = s;
            else        g_Zi[(size_t)row*24 + (o-24)] = s;
        }
    }
    __syncthreads();

    if (t < 192){
        int h = (t < 96) ? t : t - 96;
        const float* z  = (t < 96) ? sz : (sz + 24);
        const float* wr = &sws1[h][(t < 96) ? 0 : 24];
        float s = (t < 96) ? 0.f : bs1[h];
        #pragma unroll
        for (int d = 0; d < 24; d++) s = fmaf(wr[d], z[d], s);
        if (t < 96) g_Cj[(size_t)row*96 + h] = s;
        else        g_Ci[(size_t)row*96 + h] = s;
    }
}

// =================== kernel 2: pair MLP -> logits (2 j-rows per thread) ===================
// Block 256 thr = 8 warps; warp wj owns rows j0+wj and j0+8+wj; lane owns i0+lane.
// Weight LDS (12 x LDS.128 per h) amortized over 2 pairs; ciT load shared.
__global__ __launch_bounds__(256) void k_pair(
    const float* __restrict__ Ws1, const float* __restrict__ Ws2,
    const float* __restrict__ bs2)
{
    __shared__ __align__(16) u64 whs[96][24];   // packed pairs of W_s1[:,48:96]
    __shared__ float ciT[96][33];
    __shared__ float cjs[16][96];
    __shared__ float ws2s[96];
    __shared__ float ziT[24][33];
    __shared__ float zjs[16][24];
    __shared__ float sbs2;

    const int t  = threadIdx.x;
    const int b  = blockIdx.z;
    const int i0 = blockIdx.x * 32;
    const int j0 = blockIdx.y * 16;
    const int base = b * Sn;

    for (int idx = t; idx < 96*24; idx += 256){
        int h = idx / 24, p = idx % 24;
        whs[h][p] = *(const u64*)(Ws1 + h*96 + 48 + 2*p);
    }
    if (t < 96) ws2s[t] = Ws2[t];
    if (t == 0) sbs2 = bs2[0];
    for (int idx = t; idx < 16*96; idx += 256){
        int jj = idx / 96, h = idx % 96;
        cjs[jj][h] = g_Cj[(size_t)(base + j0 + jj)*96 + h];
    }
    for (int idx = t; idx < 96*32; idx += 256){
        int l = idx / 96, h = idx % 96;
        ciT[h][l] = g_Ci[(size_t)(base + i0 + l)*96 + h];
    }
    for (int idx = t; idx < 24*32; idx += 256){
        int l = idx / 24, d = idx % 24;
        ziT[d][l] = g_Zi[(size_t)(base + i0 + l)*24 + d];
    }
    for (int idx = t; idx < 16*24; idx += 256){
        int jj = idx / 24, d = idx % 24;
        zjs[jj][d] = g_Zj[(size_t)(base + j0 + jj)*24 + d];
    }
    __syncthreads();

    const int wj = t >> 5, lane = t & 31;

    u64 fA[24], fB[24];
    #pragma unroll
    for (int p = 0; p < 12; p++){
        float zi0 = ziT[2*p][lane], zi1 = ziT[2*p+1][lane];
        float a0 = zjs[wj][2*p],    a1 = zjs[wj][2*p+1];
        float b0 = zjs[wj+8][2*p],  b1 = zjs[wj+8][2*p+1];
        fA[p]      = pack2(a0*zi0, a1*zi1);
        fA[12 + p] = pack2(fabsf(a0 - zi0), fabsf(a1 - zi1));
        fB[p]      = pack2(b0*zi0, b1*zi1);
        fB[12 + p] = pack2(fabsf(b0 - zi0), fabsf(b1 - zi1));
    }

    float logitA = sbs2, logitB = sbs2;
    #pragma unroll 1
    for (int h = 0; h < 96; h++){
        float ci = ciT[h][lane];
        u64 accA0 = pack2(ci, cjs[wj][h]);
        u64 accB0 = pack2(ci, cjs[wj+8][h]);
        u64 accA1 = 0ull, accA2 = 0ull, accA3 = 0ull;
        u64 accB1 = 0ull, accB2 = 0ull, accB3 = 0ull;
        #pragma unroll
        for (int p = 0; p < 24; p += 4){
            ulonglong2 w0 = *(const ulonglong2*)&whs[h][p];
            ulonglong2 w1 = *(const ulonglong2*)&whs[h][p+2];
            accA0 = fma2(w0.x, fA[p],   accA0);
            accB0 = fma2(w0.x, fB[p],   accB0);
            accA1 = fma2(w0.y, fA[p+1], accA1);
            accB1 = fma2(w0.y, fB[p+1], accB1);
            accA2 = fma2(w1.x, fA[p+2], accA2);
            accB2 = fma2(w1.x, fB[p+2], accB2);
            accA3 = fma2(w1.y, fA[p+3], accA3);
            accB3 = fma2(w1.y, fB[p+3], accB3);
        }
        u64 sA2 = add2(add2(accA0, accA1), add2(accA2, accA3));
        u64 sB2 = add2(add2(accB0, accB1), add2(accB2, accB3));
        float2 svA = unpack2(sA2), svB = unpack2(sB2);
        float w2 = ws2s[h];
        logitA = fmaf(w2, fmaxf(svA.x + svA.y, 0.f), logitA);
        logitB = fmaf(w2, fmaxf(svB.x + svB.y, 0.f), logitB);
    }
    g_P[(size_t)(base + j0 + wj)*Sn + i0 + lane]     = logitA;
    g_P[(size_t)(base + j0 + 8 + wj)*Sn + i0 + lane] = logitB;
}

// =================== kernel 3: masked softmax over i (in place) ===================
__global__ __launch_bounds__(256) void k_softmax(const float* __restrict__ mask){
    const int r = blockIdx.x;
    const int b = r / Sn;
    float* row = g_P + (size_t)r*Sn;
    const float* mrow = mask + (size_t)b*Sn;
    const int t = threadIdx.x;
    __shared__ float red[256];

    float vals[4]; float mx = -3.402823466e38f;
    #pragma unroll
    for (int q = 0; q < 4; q++){
        int i = t + q*256;
        float v = row[i] + (1.0f - mrow[i]) * (-3.402823466e38f);
        vals[q] = v; mx = fmaxf(mx, v);
    }
    red[t] = mx; __syncthreads();
    for (int s = 128; s > 0; s >>= 1){ if (t < s) red[t] = fmaxf(red[t], red[t+s]); __syncthreads(); }
    mx = red[0]; __syncthreads();

    float sum = 0.f;
    #pragma unroll
    for (int q = 0; q < 4; q++){ vals[q] = __expf(vals[q] - mx); sum += vals[q]; }
    red[t] = sum; __syncthreads();
    for (int s = 128; s > 0; s >>= 1){ if (t < s) red[t] += red[t+s]; __syncthreads(); }
    float inv = 1.0f / red[0];
    #pragma unroll
    for (int q = 0; q < 4; q++) row[t + q*256] = vals[q] * inv;
}

// =================== unified 4-stage pipelined GEMM (f32x2) ===================
// MODE 0: ctx = P @ Hi                              (NN, K=1024, per-batch)
// MODE 1: h1  = relu([ctx,Hj,ctx*Hj] @ Wv1^T + b)   (NT, K=2304, virtual A)
// MODE 2: out = alpha*(h1 @ Wv2^T + b)              (NT, K=768)
// 128 thr, tile M=64 x N=64 x K=16. 4 smem stages, LDG prefetch distance 3
// (4 rotating register sets), unroll-by-4 so indices are compile-time.
template<int MODE>
__global__ __launch_bounds__(128) void k_gemm(
    const float* __restrict__ BW,      // MODE0: Hi; MODE1: Wv1; MODE2: Wv2
    const float* __restrict__ Hj,      // MODE1 only
    const float* __restrict__ bias,    // MODE1/2
    const float* __restrict__ alpha_p, // MODE2
    float* __restrict__ Cout)          // MODE2 output
{
    constexpr int K = (MODE == 0) ? 1024 : (MODE == 1) ? 2304 : 768;
    constexpr int T = K / 16;          // 64 / 144 / 48, all % 4 == 0
    __shared__ __align__(16) u64   As[4][16][64];
    __shared__ __align__(16) float Bs[4][16][64];

    const int t  = threadIdx.x;
    const int n0 = blockIdx.x * 64;
    const int m0 = blockIdx.y * 64;
    const int b  = (MODE == 0) ? blockIdx.z : 0;
    const int rowbase = (MODE == 0) ? b*Sn + m0 : m0;

    const int am = t >> 1, ak8 = (t & 1) * 8;       // A staging
    const int bk = t >> 3, bn8 = (t & 7) * 8;       // B staging (NN)
    const int bn = t >> 1, bk8 = (t & 1) * 8;       // B staging (NT)
    const int ty4 = (t >> 3) * 4, tx8 = (t & 7) * 8;

    const float* ArowP  = g_P   + (size_t)(rowbase + am)*Sn;
    const float* ArowC  = g_ctx + (size_t)(rowbase + am)*Hn;
    const float* ArowH  = (MODE == 1) ? (Hj + (size_t)(rowbase + am)*Hn) : (const float*)0;
    const float* ArowH1 = g_h1  + (size_t)(rowbase + am)*Hn;
    const float* Bsrc   = (MODE == 0) ? (BW + (size_t)b*Sn*Hn) : BW;

    float4 ra0[4], ra1[4], rb0[4], rb1[4];   // 4 rotating regsets

    auto ldg = [&](int k0, float4& a0, float4& a1, float4& b0, float4& b1){
        const int fo = k0 + ak8;
        if (MODE == 0){
            a0 = *(const float4*)(ArowP + fo); a1 = *(const float4*)(ArowP + fo + 4);
        } else if (MODE == 2){
            a0 = *(const float4*)(ArowH1 + fo); a1 = *(const float4*)(ArowH1 + fo + 4);
        } else {
            if (fo < 768){
                a0 = *(const float4*)(ArowC + fo); a1 = *(const float4*)(ArowC + fo + 4);
            } else if (fo < 1536){
                a0 = *(const float4*)(ArowH + fo - 768); a1 = *(const float4*)(ArowH + fo - 764);
            } else {
                float4 c0 = *(const float4*)(ArowC + fo - 1536);
                float4 c1 = *(const float4*)(ArowC + fo - 1532);
                float4 h0 = *(const float4*)(ArowH + fo - 1536);
                float4 h1v = *(const float4*)(ArowH + fo - 1532);
                a0 = make_float4(c0.x*h0.x, c0.y*h0.y, c0.z*h0.z, c0.w*h0.w);
                a1 = make_float4(c1.x*h1v.x, c1.y*h1v.y, c1.z*h1v.z, c1.w*h1v.w);
            }
        }
        if (MODE == 0){
            const float* s = Bsrc + (size_t)(k0 + bk)*Hn + n0 + bn8;
            b0 = *(const float4*)s; b1 = *(const float4*)(s + 4);
        } else {
            const float* s = Bsrc + (size_t)(n0 + bn)*K + k0 + bk8;
            b0 = *(const float4*)s; b1 = *(const float4*)(s + 4);
        }
    };
    auto sts = [&](int buf, const float4& a0, const float4& a1,
                             const float4& b0, const float4& b1){
        As[buf][ak8+0][am] = pack2(a0.x, a0.x);
        As[buf][ak8+1][am] = pack2(a0.y, a0.y);
        As[buf][ak8+2][am] = pack2(a0.z, a0.z);
        As[buf][ak8+3][am] = pack2(a0.w, a0.w);
        As[buf][ak8+4][am] = pack2(a1.x, a1.x);
        As[buf][ak8+5][am] = pack2(a1.y, a1.y);
        As[buf][ak8+6][am] = pack2(a1.z, a1.z);
        As[buf][ak8+7][am] = pack2(a1.w, a1.w);
        if (MODE == 0){
            *(float4*)&Bs[buf][bk][bn8]     = b0;
            *(float4*)&Bs[buf][bk][bn8 + 4] = b1;
        } else {
            Bs[buf][bk8+0][bn] = b0.x; Bs[buf][bk8+1][bn] = b0.y;
            Bs[buf][bk8+2][bn] = b0.z; Bs[buf][bk8+3][bn] = b0.w;
            Bs[buf][bk8+4][bn] = b1.x; Bs[buf][bk8+5][bn] = b1.y;
            Bs[buf][bk8+6][bn] = b1.z; Bs[buf][bk8+7][bn] = b1.w;
        }
    };

    u64 acc[4][4];
    #pragma unroll
    for (int m = 0; m < 4; m++)
        #pragma unroll
        for (int n = 0; n < 4; n++) acc[m][n] = 0ull;

    // prologue: stages 0..2 in flight, stage 0 committed
    ldg(0,  ra0[0], ra1[0], rb0[0], rb1[0]);
    ldg(16, ra0[1], ra1[1], rb0[1], rb1[1]);
    ldg(32, ra0[2], ra1[2], rb0[2], rb1[2]);
    sts(0, ra0[0], ra1[0], rb0[0], rb1[0]);
    __syncthreads();

    #define GEMM_BODY(q)                                                        \
    {                                                                           \
        const int tt = tb + (q);                                                \
        constexpr int CUR = (q) & 3;                                            \
        constexpr int NXT = ((q) + 1) & 3;                                      \
        constexpr int LDR = ((q) + 3) & 3;                                      \
        if (tt + 1 < T) sts(NXT, ra0[NXT], ra1[NXT], rb0[NXT], rb1[NXT]);       \
        if (tt + 3 < T) ldg((tt + 3) * 16, ra0[LDR], ra1[LDR], rb0[LDR], rb1[LDR]); \
        _Pragma("unroll")                                                       \
        for (int k = 0; k < 16; k++){                                           \
            ulonglong2 A01 = *(const ulonglong2*)&As[CUR][k][ty4];              \
            ulonglong2 A23 = *(const ulonglong2*)&As[CUR][k][ty4 + 2];          \
            ulonglong2 B01 = *(const ulonglong2*)&Bs[CUR][k][tx8];              \
            ulonglong2 B23 = *(const ulonglong2*)&Bs[CUR][k][tx8 + 4];          \
            u64 av[4] = {A01.x, A01.y, A23.x, A23.y};                           \
            u64 bv[4] = {B01.x, B01.y, B23.x, B23.y};                           \
            _Pragma("unroll")                                                   \
            for (int m = 0; m < 4; m++)                                         \
                _Pragma("unroll")                                               \
                for (int n = 0; n < 4; n++)                                     \
                    acc[m][n] = fma2(av[m], bv[n], acc[m][n]);                  \
        }                                                                       \
        __syncthreads();                                                        \
    }

    for (int tb = 0; tb < T; tb += 4){
        GEMM_BODY(0); GEMM_BODY(1); GEMM_BODY(2); GEMM_BODY(3);
    }
    #undef GEMM_BODY

    const float alpha = (MODE == 2) ? alpha_p[0] : 1.0f;
    #pragma unroll
    for (int m = 0; m < 4; m++){
        float out[8];
        #pragma unroll
        for (int n = 0; n < 4; n++){
            float2 v = unpack2(acc[m][n]);
            out[2*n] = v.x; out[2*n+1] = v.y;
        }
        const int nbase = n0 + tx8;
        if (MODE != 0){
            #pragma unroll
            for (int q = 0; q < 8; q++){
                float v = out[q] + bias[nbase + q];
                out[q] = (MODE == 1) ? fmaxf(v, 0.f) : v * alpha;
            }
        }
        float* dst;
        if      (MODE == 0) dst = &g_ctx[(size_t)(rowbase + ty4 + m)*Hn + nbase];
        else if (MODE == 1) dst = &g_h1 [(size_t)(rowbase + ty4 + m)*Hn + nbase];
        else                dst = &Cout [(size_t)(rowbase + ty4 + m)*Hn + nbase];
        *(float4*)dst       = *(float4*)&out[0];
        *(float4*)(dst + 4) = *(float4*)&out[4];
    }
}

// =============================== launch ===============================
extern "C" void kernel_launch(void* const* d_in, const int* in_sizes, int n_in,
                              void* d_out, int out_size)
{
    const float* Hj    = (const float*)d_in[0];
    const float* Hi    = (const float*)d_in[1];
    const float* mask  = (const float*)d_in[2];
    const float* Wpj   = (const float*)d_in[3];
    const float* Wpi   = (const float*)d_in[4];
    const float* Ws1   = (const float*)d_in[5];
    const float* bs1   = (const float*)d_in[6];
    const float* Ws2   = (const float*)d_in[7];
    const float* bs2   = (const float*)d_in[8];
    const float* Wv1   = (const float*)d_in[9];
    const float* bv1   = (const float*)d_in[10];
    const float* Wv2   = (const float*)d_in[11];
    const float* bv2   = (const float*)d_in[12];
    const float* alpha = (const float*)d_in[13];
    float* out = (float*)d_out;

    k_proj<<<Bn*Sn, 256>>>(Hj, Hi, Wpj, Wpi, Ws1, bs1);

    dim3 gp(Sn/32, Sn/16, Bn);
    k_pair<<<gp, 256>>>(Ws1, Ws2, bs2);

    k_softmax<<<Bn*Sn, 256>>>(mask);

    dim3 gc(Hn/64, Sn/64, Bn);
    k_gemm<0><<<gc, 128>>>(Hi, nullptr, nullptr, nullptr, nullptr);

    dim3 gv(Hn/64, (Bn*Sn)/64, 1);
    k_gemm<1><<<gv, 128>>>(Wv1, Hj, bv1, nullptr, nullptr);
    k_gemm<2><<<gv, 128>>>(Wv2, nullptr, bv2, alpha, out);
}

// round 5
// speedup vs baseline: 1.6212x; 1.2244x over previous
#include <cuda_runtime.h>
#include <cuda_bf16.h>

typedef unsigned long long u64;

#define Bn   2
#define Sn   1024
#define Hn   768
#define Dn   24
#define HIDn 96

// ---------------- scratch (static device arrays; no allocation) ----------------
__device__ float g_Zj  [Bn*Sn*Dn];
__device__ float g_Zi  [Bn*Sn*Dn];
__device__ float g_Cj  [Bn*Sn*HIDn];
__device__ float g_Ci  [Bn*Sn*HIDn];
__device__ float g_P   [Bn*Sn*Sn];     // logits -> probs (in place)
__device__ float g_ctxA[Bn*Sn*Hn];     // ctx partial (K-split half 0)
__device__ float g_ctxB[Bn*Sn*Hn];     // ctx partial (K-split half 1)
__device__ float g_h1A [Bn*Sn*Hn];     // h1 pre-activation partial 0
__device__ float g_h1B [Bn*Sn*Hn];     // h1 pre-activation partial 1

// ---------------- packed f32x2 helpers ----------------
__device__ __forceinline__ u64 pack2(float x, float y){
    u64 r;
    asm("mov.b64 %0, {%1, %2};" : "=l"(r)
        : "r"(__float_as_uint(x)), "r"(__float_as_uint(y)));
    return r;
}
__device__ __forceinline__ float2 unpack2(u64 v){
    unsigned lo, hi;
    asm("mov.b64 {%0, %1}, %2;" : "=r"(lo), "=r"(hi) : "l"(v));
    return make_float2(__uint_as_float(lo), __uint_as_float(hi));
}
__device__ __forceinline__ u64 fma2(u64 a, u64 b, u64 c){
    u64 d;
    asm("fma.rn.f32x2 %0, %1, %2, %3;" : "=l"(d) : "l"(a), "l"(b), "l"(c));
    return d;
}
__device__ __forceinline__ u64 add2(u64 a, u64 b){
    u64 d;
    asm("add.rn.f32x2 %0, %1, %2;" : "=l"(d) : "l"(a), "l"(b));
    return d;
}

// =================== kernel 1: projections + per-token MLP terms ===================
__global__ __launch_bounds__(256) void k_proj(
    const float* __restrict__ Hj, const float* __restrict__ Hi,
    const float* __restrict__ Wpj, const float* __restrict__ Wpi,
    const float* __restrict__ Ws1, const float* __restrict__ bs1)
{
    __shared__ float shj[Hn], shi[Hn];
    __shared__ float sz[48];
    __shared__ float sws1[96][97];
    const int row = blockIdx.x;
    const int t = threadIdx.x;
    const float* hj = Hj + (size_t)row*Hn;
    const float* hi = Hi + (size_t)row*Hn;
    for (int k = t; k < Hn; k += 256){ shj[k] = hj[k]; shi[k] = hi[k]; }
    for (int idx = t; idx < 96*96; idx += 256) sws1[idx/96][idx%96] = Ws1[idx];
    __syncthreads();

    const int w = t >> 5, lane = t & 31;
    for (int o = w; o < 48; o += 8){
        const float* wv = (o < 24) ? (Wpj + (size_t)o*Hn) : (Wpi + (size_t)(o-24)*Hn);
        const float* x  = (o < 24) ? shj : shi;
        float s0 = 0.f, s1 = 0.f;
        #pragma unroll
        for (int h = lane; h < Hn; h += 64){
            s0 = fmaf(wv[h],    x[h],    s0);
            s1 = fmaf(wv[h+32], x[h+32], s1);
        }
        float s = s0 + s1;
        #pragma unroll
        for (int off = 16; off; off >>= 1) s += __shfl_xor_sync(0xffffffffu, s, off);
        if (lane == 0){
            sz[o] = s;
            if (o < 24) g_Zj[(size_t)row*24 + o]      = s;
            else        g_Zi[(size_t)row*24 + (o-24)] = s;
        }
    }
    __syncthreads();

    if (t < 192){
        int h = (t < 96) ? t : t - 96;
        const float* z  = (t < 96) ? sz : (sz + 24);
        const float* wr = &sws1[h][(t < 96) ? 0 : 24];
        float s = (t < 96) ? 0.f : bs1[h];
        #pragma unroll
        for (int d = 0; d < 24; d++) s = fmaf(wr[d], z[d], s);
        if (t < 96) g_Cj[(size_t)row*96 + h] = s;
        else        g_Ci[(size_t)row*96 + h] = s;
    }
}

// =================== kernel 2: pair MLP -> logits (unchanged from R3) ===================
__global__ __launch_bounds__(256) void k_pair(
    const float* __restrict__ Ws1, const float* __restrict__ Ws2,
    const float* __restrict__ bs2)
{
    __shared__ __align__(16) u64 whs[96][24];
    __shared__ float ciT[96][33];
    __shared__ float cjs[16][96];
    __shared__ float ws2s[96];
    __shared__ float ziT[24][33];
    __shared__ float zjs[16][24];
    __shared__ float sbs2;

    const int t  = threadIdx.x;
    const int b  = blockIdx.z;
    const int i0 = blockIdx.x * 32;
    const int j0 = blockIdx.y * 16;
    const int base = b * Sn;

    for (int idx = t; idx < 96*24; idx += 256){
        int h = idx / 24, p = idx % 24;
        whs[h][p] = *(const u64*)(Ws1 + h*96 + 48 + 2*p);
    }
    if (t < 96) ws2s[t] = Ws2[t];
    if (t == 0) sbs2 = bs2[0];
    for (int idx = t; idx < 16*96; idx += 256){
        int jj = idx / 96, h = idx % 96;
        cjs[jj][h] = g_Cj[(size_t)(base + j0 + jj)*96 + h];
    }
    for (int idx = t; idx < 96*32; idx += 256){
        int l = idx / 96, h = idx % 96;
        ciT[h][l] = g_Ci[(size_t)(base + i0 + l)*96 + h];
    }
    for (int idx = t; idx < 24*32; idx += 256){
        int l = idx / 24, d = idx % 24;
        ziT[d][l] = g_Zi[(size_t)(base + i0 + l)*24 + d];
    }
    for (int idx = t; idx < 16*24; idx += 256){
        int jj = idx / 24, d = idx % 24;
        zjs[jj][d] = g_Zj[(size_t)(base + j0 + jj)*24 + d];
    }
    __syncthreads();

    const int wj = t >> 5, lane = t & 31;

    u64 fA[24], fB[24];
    #pragma unroll
    for (int p = 0; p < 12; p++){
        float zi0 = ziT[2*p][lane], zi1 = ziT[2*p+1][lane];
        float a0 = zjs[wj][2*p],    a1 = zjs[wj][2*p+1];
        float b0 = zjs[wj+8][2*p],  b1 = zjs[wj+8][2*p+1];
        fA[p]      = pack2(a0*zi0, a1*zi1);
        fA[12 + p] = pack2(fabsf(a0 - zi0), fabsf(a1 - zi1));
        fB[p]      = pack2(b0*zi0, b1*zi1);
        fB[12 + p] = pack2(fabsf(b0 - zi0), fabsf(b1 - zi1));
    }

    float logitA = sbs2, logitB = sbs2;
    #pragma unroll 1
    for (int h = 0; h < 96; h++){
        float ci = ciT[h][lane];
        u64 accA0 = pack2(ci, cjs[wj][h]);
        u64 accB0 = pack2(ci, cjs[wj+8][h]);
        u64 accA1 = 0ull, accA2 = 0ull, accA3 = 0ull;
        u64 accB1 = 0ull, accB2 = 0ull, accB3 = 0ull;
        #pragma unroll
        for (int p = 0; p < 24; p += 4){
            ulonglong2 w0 = *(const ulonglong2*)&whs[h][p];
            ulonglong2 w1 = *(const ulonglong2*)&whs[h][p+2];
            accA0 = fma2(w0.x, fA[p],   accA0);
            accB0 = fma2(w0.x, fB[p],   accB0);
            accA1 = fma2(w0.y, fA[p+1], accA1);
            accB1 = fma2(w0.y, fB[p+1], accB1);
            accA2 = fma2(w1.x, fA[p+2], accA2);
            accB2 = fma2(w1.x, fB[p+2], accB2);
            accA3 = fma2(w1.y, fA[p+3], accA3);
            accB3 = fma2(w1.y, fB[p+3], accB3);
        }
        u64 sA2 = add2(add2(accA0, accA1), add2(accA2, accA3));
        u64 sB2 = add2(add2(accB0, accB1), add2(accB2, accB3));
        float2 svA = unpack2(sA2), svB = unpack2(sB2);
        float w2 = ws2s[h];
        logitA = fmaf(w2, fmaxf(svA.x + svA.y, 0.f), logitA);
        logitB = fmaf(w2, fmaxf(svB.x + svB.y, 0.f), logitB);
    }
    g_P[(size_t)(base + j0 + wj)*Sn + i0 + lane]     = logitA;
    g_P[(size_t)(base + j0 + 8 + wj)*Sn + i0 + lane] = logitB;
}

// =================== kernel 3: masked softmax over i (in place) ===================
__global__ __launch_bounds__(256) void k_softmax(const float* __restrict__ mask){
    const int r = blockIdx.x;
    const int b = r / Sn;
    float* row = g_P + (size_t)r*Sn;
    const float* mrow = mask + (size_t)b*Sn;
    const int t = threadIdx.x;
    __shared__ float red[256];

    float vals[4]; float mx = -3.402823466e38f;
    #pragma unroll
    for (int q = 0; q < 4; q++){
        int i = t + q*256;
        float v = row[i] + (1.0f - mrow[i]) * (-3.402823466e38f);
        vals[q] = v; mx = fmaxf(mx, v);
    }
    red[t] = mx; __syncthreads();
    for (int s = 128; s > 0; s >>= 1){ if (t < s) red[t] = fmaxf(red[t], red[t+s]); __syncthreads(); }
    mx = red[0]; __syncthreads();

    float sum = 0.f;
    #pragma unroll
    for (int q = 0; q < 4; q++){ vals[q] = __expf(vals[q] - mx); sum += vals[q]; }
    red[t] = sum; __syncthreads();
    for (int s = 128; s > 0; s >>= 1){ if (t < s) red[t] += red[t+s]; __syncthreads(); }
    float inv = 1.0f / red[0];
    #pragma unroll
    for (int q = 0; q < 4; q++) row[t + q*256] = vals[q] * inv;
}

// =================== balanced f32x2 GEMM, tile 64m x 128n, 8x8/thread ===================
// acc packs m-pairs (A read as natural u64 pairs from smem floats);
// B read scalar + register-duplicated (ALU pipe). smem:fma balanced 1:1.
// MODE 0: ctx partial = P[:, kslice] @ Hi[kslice, :]          (K=512 per half)
// MODE 1: h1 partial  = feat[:, kslice] @ Wv1[:, kslice]^T    (K=1152 per half, virtual A)
// MODE 2: out = alpha*( relu(h1A+h1B+bv1) @ Wv2^T + bv2 )     (K=768)
template<int MODE>
__global__ __launch_bounds__(128) void k_gemm(
    const float* __restrict__ BW,      // MODE0: Hi; MODE1: Wv1; MODE2: Wv2
    const float* __restrict__ Hj,      // MODE1 only
    const float* __restrict__ bias,    // MODE1: unused; MODE2: bv1 (A-side relu bias)
    const float* __restrict__ bias2,   // MODE2: bv2
    const float* __restrict__ alpha_p, // MODE2
    float* __restrict__ Cout)          // MODE2: d_out
{
    constexpr int KH = (MODE == 0) ? 512 : (MODE == 1) ? 1152 : 768;  // K per launch slice
    constexpr int T  = KH / 16;
    __shared__ __align__(16) u64   As[2][16][32];   // viewed as float [16][64]
    __shared__ __align__(16) float Bs[2][16][128];

    const int t  = threadIdx.x;
    const int n0 = blockIdx.x * 128;
    const int m0 = blockIdx.y * 64;
    int b = 0, ks = 0;
    if (MODE == 0){ b = blockIdx.z >> 1; ks = blockIdx.z & 1; }
    if (MODE == 1){ ks = blockIdx.z; }
    const int rowbase = (MODE == 0) ? b*Sn + m0 : m0;
    const int kbase   = ks * KH;

    // staging coords
    const int am = t >> 1, ah8 = (t & 1) * 8;          // A: row am (64), 8 k-floats
    const int b0r = t >> 3, b0c = (t & 7) * 16;        // B NN: row (16), 16 cols
    const int ty = t >> 4, tx = t & 15;                // compute: 8 m x 8 n

    const float* ArowP  = g_P    + (size_t)(rowbase + am)*Sn + kbase;
    const float* ArowCA = g_ctxA + (size_t)(rowbase + am)*Hn;
    const float* ArowCB = g_ctxB + (size_t)(rowbase + am)*Hn;
    const float* ArowH  = (MODE == 1) ? (Hj + (size_t)(rowbase + am)*Hn) : (const float*)0;
    const float* ArowA  = g_h1A  + (size_t)(rowbase + am)*Hn;
    const float* ArowB  = g_h1B  + (size_t)(rowbase + am)*Hn;
    const float* Bsrc   = (MODE == 0) ? (BW + (size_t)b*Sn*Hn) : BW;

    float4 ra0, ra1;          // A regs: 8 floats
    float4 rb0, rb1, rb2, rb3; // B regs: 16 floats

    auto ldg = [&](int kt){   // kt = tile index within this launch's slice
        const int kb = kt * 16;
        // ---- A: 8 floats at (row am, cols kb+ah8 .. +8) ----
        if (MODE == 0){
            ra0 = *(const float4*)(ArowP + kb + ah8);
            ra1 = *(const float4*)(ArowP + kb + ah8 + 4);
        } else if (MODE == 2){
            const int fo = kb + ah8;
            float4 xa0 = *(const float4*)(ArowA + fo);
            float4 xa1 = *(const float4*)(ArowA + fo + 4);
            float4 xb0 = *(const float4*)(ArowB + fo);
            float4 xb1 = *(const float4*)(ArowB + fo + 4);
            float4 bb0 = *(const float4*)(bias + fo);
            float4 bb1 = *(const float4*)(bias + fo + 4);
            ra0 = make_float4(fmaxf(xa0.x+xb0.x+bb0.x,0.f), fmaxf(xa0.y+xb0.y+bb0.y,0.f),
                              fmaxf(xa0.z+xb0.z+bb0.z,0.f), fmaxf(xa0.w+xb0.w+bb0.w,0.f));
            ra1 = make_float4(fmaxf(xa1.x+xb1.x+bb1.x,0.f), fmaxf(xa1.y+xb1.y+bb1.y,0.f),
                              fmaxf(xa1.z+xb1.z+bb1.z,0.f), fmaxf(xa1.w+xb1.w+bb1.w,0.f));
        } else { // MODE 1: virtual feature row, global feature offset
            const int fo = kbase + kb + ah8;
            if (fo < 768){
                float4 c0 = *(const float4*)(ArowCA + fo);
                float4 c1 = *(const float4*)(ArowCA + fo + 4);
                float4 d0 = *(const float4*)(ArowCB + fo);
                float4 d1 = *(const float4*)(ArowCB + fo + 4);
                ra0 = make_float4(c0.x+d0.x, c0.y+d0.y, c0.z+d0.z, c0.w+d0.w);
                ra1 = make_float4(c1.x+d1.x, c1.y+d1.y, c1.z+d1.z, c1.w+d1.w);
            } else if (fo < 1536){
                ra0 = *(const float4*)(ArowH + fo - 768);
                ra1 = *(const float4*)(ArowH + fo - 764);
            } else {
                const int go = fo - 1536;
                float4 c0 = *(const float4*)(ArowCA + go);
                float4 c1 = *(const float4*)(ArowCA + go + 4);
                float4 d0 = *(const float4*)(ArowCB + go);
                float4 d1 = *(const float4*)(ArowCB + go + 4);
                float4 h0 = *(const float4*)(ArowH + go);
                float4 h1 = *(const float4*)(ArowH + go + 4);
                ra0 = make_float4((c0.x+d0.x)*h0.x, (c0.y+d0.y)*h0.y,
                                  (c0.z+d0.z)*h0.z, (c0.w+d0.w)*h0.w);
                ra1 = make_float4((c1.x+d1.x)*h1.x, (c1.y+d1.y)*h1.y,
                                  (c1.z+d1.z)*h1.z, (c1.w+d1.w)*h1.w);
            }
        }
        // ---- B: 16 floats ----
        if (MODE == 0){
            const float* s = Bsrc + (size_t)(kbase + kb + b0r)*Hn + n0 + b0c;
            rb0 = *(const float4*)s;       rb1 = *(const float4*)(s + 4);
            rb2 = *(const float4*)(s + 8); rb3 = *(const float4*)(s + 12);
        } else {
            constexpr int KW = (MODE == 1) ? 2304 : 768;   // W row stride
            const float* s = Bsrc + (size_t)(n0 + t)*KW + kbase + kb;
            rb0 = *(const float4*)s;       rb1 = *(const float4*)(s + 4);
            rb2 = *(const float4*)(s + 8); rb3 = *(const float4*)(s + 12);
        }
    };
    auto sts = [&](int buf){
        float* Af = (float*)&As[buf][0][0];   // [16][64]
        Af[(ah8+0)*64 + am] = ra0.x; Af[(ah8+1)*64 + am] = ra0.y;
        Af[(ah8+2)*64 + am] = ra0.z; Af[(ah8+3)*64 + am] = ra0.w;
        Af[(ah8+4)*64 + am] = ra1.x; Af[(ah8+5)*64 + am] = ra1.y;
        Af[(ah8+6)*64 + am] = ra1.z; Af[(ah8+7)*64 + am] = ra1.w;
        if (MODE == 0){
            float* d = &Bs[buf][b0r][b0c];
            *(float4*)d = rb0; *(float4*)(d+4) = rb1;
            *(float4*)(d+8) = rb2; *(float4*)(d+12) = rb3;
        } else {
            Bs[buf][ 0][t] = rb0.x; Bs[buf][ 1][t] = rb0.y;
            Bs[buf][ 2][t] = rb0.z; Bs[buf][ 3][t] = rb0.w;
            Bs[buf][ 4][t] = rb1.x; Bs[buf][ 5][t] = rb1.y;
            Bs[buf][ 6][t] = rb1.z; Bs[buf][ 7][t] = rb1.w;
            Bs[buf][ 8][t] = rb2.x; Bs[buf][ 9][t] = rb2.y;
            Bs[buf][10][t] = rb2.z; Bs[buf][11][t] = rb2.w;
            Bs[buf][12][t] = rb3.x; Bs[buf][13][t] = rb3.y;
            Bs[buf][14][t] = rb3.z; Bs[buf][15][t] = rb3.w;
        }
    };

    u64 acc[4][8];
    #pragma unroll
    for (int m = 0; m < 4; m++)
        #pragma unroll
        for (int n = 0; n < 8; n++) acc[m][n] = 0ull;

    ldg(0); sts(0); __syncthreads();

    for (int tt = 0; tt < T; tt++){
        const int cur = tt & 1;
        if (tt + 1 < T) ldg(tt + 1);
        #pragma unroll
        for (int k = 0; k < 16; k++){
            ulonglong2 A01 = *(const ulonglong2*)&As[cur][k][ty*4];
            ulonglong2 A23 = *(const ulonglong2*)&As[cur][k][ty*4 + 2];
            float4 bq0 = *(const float4*)&Bs[cur][k][tx*8];
            float4 bq1 = *(const float4*)&Bs[cur][k][tx*8 + 4];
            u64 av[4] = {A01.x, A01.y, A23.x, A23.y};
            u64 bd[8] = {pack2(bq0.x,bq0.x), pack2(bq0.y,bq0.y),
                         pack2(bq0.z,bq0.z), pack2(bq0.w,bq0.w),
                         pack2(bq1.x,bq1.x), pack2(bq1.y,bq1.y),
                         pack2(bq1.z,bq1.z), pack2(bq1.w,bq1.w)};
            #pragma unroll
            for (int m = 0; m < 4; m++)
                #pragma unroll
                for (int n = 0; n < 8; n++)
                    acc[m][n] = fma2(av[m], bd[n], acc[m][n]);
        }
        __syncthreads();
        if (tt + 1 < T){ sts(cur ^ 1); __syncthreads(); }
    }

    // epilogue: rows m0+ty*8+r (r=0..7), cols n0+tx*8+q (q=0..7)
    const float alpha = (MODE == 2) ? alpha_p[0] : 1.0f;
    const int nbase = n0 + tx*8;
    float badd[8];
    if (MODE == 2){
        float4 v0 = *(const float4*)(bias2 + nbase);
        float4 v1 = *(const float4*)(bias2 + nbase + 4);
        badd[0]=v0.x; badd[1]=v0.y; badd[2]=v0.z; badd[3]=v0.w;
        badd[4]=v1.x; badd[5]=v1.y; badd[6]=v1.z; badd[7]=v1.w;
    }
    #pragma unroll
    for (int r = 0; r < 8; r++){
        const int mp = r >> 1, part = r & 1;
        float out[8];
        #pragma unroll
        for (int q = 0; q < 8; q++){
            float2 v = unpack2(acc[mp][q]);
            out[q] = part ? v.y : v.x;
        }
        if (MODE == 2){
            #pragma unroll
            for (int q = 0; q < 8; q++) out[q] = (out[q] + badd[q]) * alpha;
        }
        float* dst;
        const size_t roff = (size_t)(rowbase + ty*8 + r)*Hn + nbase;
        if      (MODE == 0) dst = (ks == 0 ? g_ctxA : g_ctxB) + roff;
        else if (MODE == 1) dst = (ks == 0 ? g_h1A  : g_h1B ) + roff;
        else                dst = Cout + roff;
        *(float4*)dst       = *(float4*)&out[0];
        *(float4*)(dst + 4) = *(float4*)&out[4];
    }
}

// =============================== launch ===============================
extern "C" void kernel_launch(void* const* d_in, const int* in_sizes, int n_in,
                              void* d_out, int out_size)
{
    const float* Hj    = (const float*)d_in[0];
    const float* Hi    = (const float*)d_in[1];
    const float* mask  = (const float*)d_in[2];
    const float* Wpj   = (const float*)d_in[3];
    const float* Wpi   = (const float*)d_in[4];
    const float* Ws1   = (const float*)d_in[5];
    const float* bs1   = (const float*)d_in[6];
    const float* Ws2   = (const float*)d_in[7];
    const float* bs2   = (const float*)d_in[8];
    const float* Wv1   = (const float*)d_in[9];
    const float* bv1   = (const float*)d_in[10];
    const float* Wv2   = (const float*)d_in[11];
    const float* bv2   = (const float*)d_in[12];
    const float* alpha = (const float*)d_in[13];
    float* out = (float*)d_out;

    k_proj<<<Bn*Sn, 256>>>(Hj, Hi, Wpj, Wpi, Ws1, bs1);

    dim3 gp(Sn/32, Sn/16, Bn);
    k_pair<<<gp, 256>>>(Ws1, Ws2, bs2);

    k_softmax<<<Bn*Sn, 256>>>(mask);

    // ctx partials: K=1024 split x2, per batch -> z = b*2 + ks
    dim3 g0(Hn/128, Sn/64, Bn*2);
    k_gemm<0><<<g0, 128>>>(Hi, nullptr, nullptr, nullptr, nullptr, nullptr);

    // h1 partials: K=2304 split x2 -> z = ks
    dim3 g1(Hn/128, (Bn*Sn)/64, 2);
    k_gemm<1><<<g1, 128>>>(Wv1, Hj, nullptr, nullptr, nullptr, nullptr);

    // final: fuses relu(h1A+h1B+bv1), K=768
    dim3 g2(Hn/128, (Bn*Sn)/64, 1);
    k_gemm<2><<<g2, 128>>>(Wv2, nullptr, bv1, bv2, alpha, out);
}

// round 7
// speedup vs baseline: 1.7780x; 1.0967x over previous
#include <cuda_runtime.h>
#include <cuda_bf16.h>

typedef unsigned long long u64;

#define Bn   2
#define Sn   1024
#define Hn   768
#define Dn   24
#define HIDn 96

// ---------------- scratch ----------------
__device__ float g_Zj  [Bn*Sn*Dn];
__device__ float g_Zi  [Bn*Sn*Dn];
__device__ float g_Cj  [Bn*Sn*HIDn];
__device__ float g_Ci  [Bn*Sn*HIDn];
__device__ float g_P   [Bn*Sn*Sn];
__device__ float g_ctxA[Bn*Sn*Hn];
__device__ float g_ctxB[Bn*Sn*Hn];
__device__ float g_h1A [Bn*Sn*Hn];
__device__ float g_h1B [Bn*Sn*Hn];

// ---------------- packed f32x2 helpers ----------------
__device__ __forceinline__ u64 pack2(float x, float y){
    u64 r;
    asm("mov.b64 %0, {%1, %2};" : "=l"(r)
        : "r"(__float_as_uint(x)), "r"(__float_as_uint(y)));
    return r;
}
__device__ __forceinline__ float2 unpack2(u64 v){
    unsigned lo, hi;
    asm("mov.b64 {%0, %1}, %2;" : "=r"(lo), "=r"(hi) : "l"(v));
    return make_float2(__uint_as_float(lo), __uint_as_float(hi));
}
__device__ __forceinline__ u64 fma2(u64 a, u64 b, u64 c){
    u64 d;
    asm("fma.rn.f32x2 %0, %1, %2, %3;" : "=l"(d) : "l"(a), "l"(b), "l"(c));
    return d;
}
__device__ __forceinline__ u64 add2(u64 a, u64 b){
    u64 d;
    asm("add.rn.f32x2 %0, %1, %2;" : "=l"(d) : "l"(a), "l"(b));
    return d;
}

// conflict-free B column swizzle: thread tx reads its 8 cols as two
// contiguous float4 groups at [tx*4] and [64+tx*4]
__device__ __forceinline__ int swzB(int n){
    return ((n >> 2) & 1) * 64 + ((n >> 3) << 2) + (n & 3);
}

// =================== kernel 1: projections + per-token MLP terms ===================
__global__ __launch_bounds__(256) void k_proj(
    const float* __restrict__ Hj, const float* __restrict__ Hi,
    const float* __restrict__ Wpj, const float* __restrict__ Wpi,
    const float* __restrict__ Ws1, const float* __restrict__ bs1)
{
    __shared__ float shj[Hn], shi[Hn];
    __shared__ float sz[48];
    __shared__ float sws1[96][97];
    const int row = blockIdx.x;
    const int t = threadIdx.x;
    const float* hj = Hj + (size_t)row*Hn;
    const float* hi = Hi + (size_t)row*Hn;
    for (int k = t; k < Hn; k += 256){ shj[k] = hj[k]; shi[k] = hi[k]; }
    for (int idx = t; idx < 96*96; idx += 256) sws1[idx/96][idx%96] = Ws1[idx];
    __syncthreads();

    const int w = t >> 5, lane = t & 31;
    for (int o = w; o < 48; o += 8){
        const float* wv = (o < 24) ? (Wpj + (size_t)o*Hn) : (Wpi + (size_t)(o-24)*Hn);
        const float* x  = (o < 24) ? shj : shi;
        float s0 = 0.f, s1 = 0.f;
        #pragma unroll
        for (int h = lane; h < Hn; h += 64){
            s0 = fmaf(wv[h],    x[h],    s0);
            s1 = fmaf(wv[h+32], x[h+32], s1);
        }
        float s = s0 + s1;
        #pragma unroll
        for (int off = 16; off; off >>= 1) s += __shfl_xor_sync(0xffffffffu, s, off);
        if (lane == 0){
            sz[o] = s;
            if (o < 24) g_Zj[(size_t)row*24 + o]      = s;
            else        g_Zi[(size_t)row*24 + (o-24)] = s;
        }
    }
    __syncthreads();

    if (t < 192){
        int h = (t < 96) ? t : t - 96;
        const float* z  = (t < 96) ? sz : (sz + 24);
        const float* wr = &sws1[h][(t < 96) ? 0 : 24];
        float s = (t < 96) ? 0.f : bs1[h];
        #pragma unroll
        for (int d = 0; d < 24; d++) s = fmaf(wr[d], z[d], s);
        if (t < 96) g_Cj[(size_t)row*96 + h] = s;
        else        g_Ci[(size_t)row*96 + h] = s;
    }
}

// =================== kernel 2: pair MLP -> logits ===================
__global__ __launch_bounds__(256) void k_pair(
    const float* __restrict__ Ws1, const float* __restrict__ Ws2,
    const float* __restrict__ bs2)
{
    __shared__ __align__(16) u64 whs[96][24];
    __shared__ float ciT[96][33];
    __shared__ float cjs[16][96];
    __shared__ float ws2s[96];
    __shared__ float ziT[24][33];
    __shared__ float zjs[16][24];
    __shared__ float sbs2;

    const int t  = threadIdx.x;
    const int b  = blockIdx.z;
    const int i0 = blockIdx.x * 32;
    const int j0 = blockIdx.y * 16;
    const int base = b * Sn;

    for (int idx = t; idx < 96*24; idx += 256){
        int h = idx / 24, p = idx % 24;
        whs[h][p] = *(const u64*)(Ws1 + h*96 + 48 + 2*p);
    }
    if (t < 96) ws2s[t] = Ws2[t];
    if (t == 0) sbs2 = bs2[0];
    for (int idx = t; idx < 16*96; idx += 256){
        int jj = idx / 96, h = idx % 96;
        cjs[jj][h] = g_Cj[(size_t)(base + j0 + jj)*96 + h];
    }
    for (int idx = t; idx < 96*32; idx += 256){
        int l = idx / 96, h = idx % 96;
        ciT[h][l] = g_Ci[(size_t)(base + i0 + l)*96 + h];
    }
    for (int idx = t; idx < 24*32; idx += 256){
        int l = idx / 24, d = idx % 24;
        ziT[d][l] = g_Zi[(size_t)(base + i0 + l)*24 + d];
    }
    for (int idx = t; idx < 16*24; idx += 256){
        int jj = idx / 24, d = idx % 24;
        zjs[jj][d] = g_Zj[(size_t)(base + j0 + jj)*24 + d];
    }
    __syncthreads();

    const int wj = t >> 5, lane = t & 31;

    u64 fA[24], fB[24];
    #pragma unroll
    for (int p = 0; p < 12; p++){
        float zi0 = ziT[2*p][lane], zi1 = ziT[2*p+1][lane];
        float a0 = zjs[wj][2*p],    a1 = zjs[wj][2*p+1];
        float b0 = zjs[wj+8][2*p],  b1 = zjs[wj+8][2*p+1];
        fA[p]      = pack2(a0*zi0, a1*zi1);
        fA[12 + p] = pack2(fabsf(a0 - zi0), fabsf(a1 - zi1));
        fB[p]      = pack2(b0*zi0, b1*zi1);
        fB[12 + p] = pack2(fabsf(b0 - zi0), fabsf(b1 - zi1));
    }

    float logitA = sbs2, logitB = sbs2;
    #pragma unroll 1
    for (int h = 0; h < 96; h++){
        float ci = ciT[h][lane];
        u64 accA0 = pack2(ci, cjs[wj][h]);
        u64 accB0 = pack2(ci, cjs[wj+8][h]);
        u64 accA1 = 0ull, accB1 = 0ull;
        #pragma unroll
        for (int p = 0; p < 24; p += 4){
            ulonglong2 w0 = *(const ulonglong2*)&whs[h][p];
            ulonglong2 w1 = *(const ulonglong2*)&whs[h][p+2];
            accA0 = fma2(w0.x, fA[p],   accA0);
            accB0 = fma2(w0.x, fB[p],   accB0);
            accA1 = fma2(w0.y, fA[p+1], accA1);
            accB1 = fma2(w0.y, fB[p+1], accB1);
            accA0 = fma2(w1.x, fA[p+2], accA0);
            accB0 = fma2(w1.x, fB[p+2], accB0);
            accA1 = fma2(w1.y, fA[p+3], accA1);
            accB1 = fma2(w1.y, fB[p+3], accB1);
        }
        u64 sA2 = add2(accA0, accA1);
        u64 sB2 = add2(accB0, accB1);
        float2 svA = unpack2(sA2), svB = unpack2(sB2);
        float w2 = ws2s[h];
        logitA = fmaf(w2, fmaxf(svA.x + svA.y, 0.f), logitA);
        logitB = fmaf(w2, fmaxf(svB.x + svB.y, 0.f), logitB);
    }
    g_P[(size_t)(base + j0 + wj)*Sn + i0 + lane]     = logitA;
    g_P[(size_t)(base + j0 + 8 + wj)*Sn + i0 + lane] = logitB;
}

// =================== kernel 3: masked softmax over i (in place) ===================
__global__ __launch_bounds__(256) void k_softmax(const float* __restrict__ mask){
    const int r = blockIdx.x;
    const int b = r / Sn;
    float* row = g_P + (size_t)r*Sn;
    const float* mrow = mask + (size_t)b*Sn;
    const int t = threadIdx.x;
    __shared__ float red[256];

    float vals[4]; float mx = -3.402823466e38f;
    #pragma unroll
    for (int q = 0; q < 4; q++){
        int i = t + q*256;
        float v = row[i] + (1.0f - mrow[i]) * (-3.402823466e38f);
        vals[q] = v; mx = fmaxf(mx, v);
    }
    red[t] = mx; __syncthreads();
    for (int s = 128; s > 0; s >>= 1){ if (t < s) red[t] = fmaxf(red[t], red[t+s]); __syncthreads(); }
    mx = red[0]; __syncthreads();

    float sum = 0.f;
    #pragma unroll
    for (int q = 0; q < 4; q++){ vals[q] = __expf(vals[q] - mx); sum += vals[q]; }
    red[t] = sum; __syncthreads();
    for (int s = 128; s > 0; s >>= 1){ if (t < s) red[t] += red[t+s]; __syncthreads(); }
    float inv = 1.0f / red[0];
    #pragma unroll
    for (int q = 0; q < 4; q++) row[t + q*256] = vals[q] * inv;
}

// =================== balanced f32x2 GEMM, 64m x 128n, 8x8/thread, swizzled B ===================
// MODE 0: ctx partial = P[:, ks] @ Hi[ks, :]            (K=512 per half)
// MODE 1: h1 partial  = feat[:, ks] @ Wv1[:, ks]^T      (K=1152 per half)
// MODE 2: out = alpha*( relu(h1A+h1B+bv1) @ Wv2^T + bv2 )  (K=768)
template<int MODE>
__global__ __launch_bounds__(128) void k_gemm(
    const float* __restrict__ BW,
    const float* __restrict__ Hj,
    const float* __restrict__ bias,    // MODE2: bv1
    const float* __restrict__ bias2,   // MODE2: bv2
    const float* __restrict__ alpha_p,
    float* __restrict__ Cout)
{
    constexpr int KH = (MODE == 0) ? 512 : (MODE == 1) ? 1152 : 768;
    constexpr int T  = KH / 16;
    __shared__ __align__(16) float As[2][16][64];
    __shared__ __align__(16) float Bs[2][16][128];   // swizzled columns

    const int t  = threadIdx.x;
    const int n0 = blockIdx.x * 128;
    const int m0 = blockIdx.y * 64;
    int b = 0, ks = 0;
    if (MODE == 0){ b = blockIdx.z >> 1; ks = blockIdx.z & 1; }
    if (MODE == 1){ ks = blockIdx.z; }
    const int rowbase = (MODE == 0) ? b*Sn + m0 : m0;
    const int kbase   = ks * KH;

    const int am = t >> 1, ah8 = (t & 1) * 8;
    const int b0r = t >> 3, b0q = (t & 7);           // MODE0: row, 16-col group
    const int ty = t >> 4, tx = t & 15;
    const int swt = swzB(t & 127);                   // MODE1/2 staging column

    const float* ArowP  = g_P    + (size_t)(rowbase + am)*Sn + kbase;
    const float* ArowCA = g_ctxA + (size_t)(rowbase + am)*Hn;
    const float* ArowCB = g_ctxB + (size_t)(rowbase + am)*Hn;
    const float* ArowH  = (MODE == 1) ? (Hj + (size_t)(rowbase + am)*Hn) : (const float*)0;
    const float* ArowA  = g_h1A  + (size_t)(rowbase + am)*Hn;
    const float* ArowB  = g_h1B  + (size_t)(rowbase + am)*Hn;
    const float* Bsrc   = (MODE == 0) ? (BW + (size_t)b*Sn*Hn) : BW;

    float4 ra0, ra1, rb0, rb1, rb2, rb3;

    auto ldg = [&](int kt){
        const int kb = kt * 16;
        if (MODE == 0){
            ra0 = *(const float4*)(ArowP + kb + ah8);
            ra1 = *(const float4*)(ArowP + kb + ah8 + 4);
        } else if (MODE == 2){
            const int fo = kb + ah8;
            float4 xa0 = *(const float4*)(ArowA + fo);
            float4 xa1 = *(const float4*)(ArowA + fo + 4);
            float4 xb0 = *(const float4*)(ArowB + fo);
            float4 xb1 = *(const float4*)(ArowB + fo + 4);
            float4 bb0 = *(const float4*)(bias + fo);
            float4 bb1 = *(const float4*)(bias + fo + 4);
            ra0 = make_float4(fmaxf(xa0.x+xb0.x+bb0.x,0.f), fmaxf(xa0.y+xb0.y+bb0.y,0.f),
                              fmaxf(xa0.z+xb0.z+bb0.z,0.f), fmaxf(xa0.w+xb0.w+bb0.w,0.f));
            ra1 = make_float4(fmaxf(xa1.x+xb1.x+bb1.x,0.f), fmaxf(xa1.y+xb1.y+bb1.y,0.f),
                              fmaxf(xa1.z+xb1.z+bb1.z,0.f), fmaxf(xa1.w+xb1.w+bb1.w,0.f));
        } else {
            const int fo = kbase + kb + ah8;
            if (fo < 768){
                float4 c0 = *(const float4*)(ArowCA + fo);
                float4 c1 = *(const float4*)(ArowCA + fo + 4);
                float4 d0 = *(const float4*)(ArowCB + fo);
                float4 d1 = *(const float4*)(ArowCB + fo + 4);
                ra0 = make_float4(c0.x+d0.x, c0.y+d0.y, c0.z+d0.z, c0.w+d0.w);
                ra1 = make_float4(c1.x+d1.x, c1.y+d1.y, c1.z+d1.z, c1.w+d1.w);
            } else if (fo < 1536){
                ra0 = *(const float4*)(ArowH + fo - 768);
                ra1 = *(const float4*)(ArowH + fo - 764);
            } else {
                const int go = fo - 1536;
                float4 c0 = *(const float4*)(ArowCA + go);
                float4 c1 = *(const float4*)(ArowCA + go + 4);
                float4 d0 = *(const float4*)(ArowCB + go);
                float4 d1 = *(const float4*)(ArowCB + go + 4);
                float4 h0 = *(const float4*)(ArowH + go);
                float4 h1 = *(const float4*)(ArowH + go + 4);
                ra0 = make_float4((c0.x+d0.x)*h0.x, (c0.y+d0.y)*h0.y,
                                  (c0.z+d0.z)*h0.z, (c0.w+d0.w)*h0.w);
                ra1 = make_float4((c1.x+d1.x)*h1.x, (c1.y+d1.y)*h1.y,
                                  (c1.z+d1.z)*h1.z, (c1.w+d1.w)*h1.w);
            }
        }
        if (MODE == 0){
            const float* s = Bsrc + (size_t)(kbase + kb + b0r)*Hn + n0 + b0q*16;
            rb0 = *(const float4*)s;       rb1 = *(const float4*)(s + 4);
            rb2 = *(const float4*)(s + 8); rb3 = *(const float4*)(s + 12);
        } else {
            constexpr int KW = (MODE == 1) ? 2304 : 768;
            const float* s = Bsrc + (size_t)(n0 + t)*KW + kbase + kb;
            rb0 = *(const float4*)s;       rb1 = *(const float4*)(s + 4);
            rb2 = *(const float4*)(s + 8); rb3 = *(const float4*)(s + 12);
        }
    };
    auto sts = [&](int buf){
        float* Af = &As[buf][0][0];
        Af[(ah8+0)*64 + am] = ra0.x; Af[(ah8+1)*64 + am] = ra0.y;
        Af[(ah8+2)*64 + am] = ra0.z; Af[(ah8+3)*64 + am] = ra0.w;
        Af[(ah8+4)*64 + am] = ra1.x; Af[(ah8+5)*64 + am] = ra1.y;
        Af[(ah8+6)*64 + am] = ra1.z; Af[(ah8+7)*64 + am] = ra1.w;
        if (MODE == 0){
            // cols c..c+15 (c = 16*b0q) -> swizzled float4 groups
            float* d = &Bs[buf][b0r][0];
            *(float4*)(d + 8*b0q)          = rb0;   // cols c..c+3   (g0)
            *(float4*)(d + 64 + 8*b0q)     = rb1;   // cols c+4..c+7 (g1)
            *(float4*)(d + 8*b0q + 4)      = rb2;   // cols c+8..11  (g0)
            *(float4*)(d + 64 + 8*b0q + 4) = rb3;   // cols c+12..15 (g1)
        } else {
            Bs[buf][ 0][swt] = rb0.x; Bs[buf][ 1][swt] = rb0.y;
            Bs[buf][ 2][swt] = rb0.z; Bs[buf][ 3][swt] = rb0.w;
            Bs[buf][ 4][swt] = rb1.x; Bs[buf][ 5][swt] = rb1.y;
            Bs[buf][ 6][swt] = rb1.z; Bs[buf][ 7][swt] = rb1.w;
            Bs[buf][ 8][swt] = rb2.x; Bs[buf][ 9][swt] = rb2.y;
            Bs[buf][10][swt] = rb2.z; Bs[buf][11][swt] = rb2.w;
            Bs[buf][12][swt] = rb3.x; Bs[buf][13][swt] = rb3.y;
            Bs[buf][14][swt] = rb3.z; Bs[buf][15][swt] = rb3.w;
        }
    };

    u64 acc[4][8];
    #pragma unroll
    for (int m = 0; m < 4; m++)
        #pragma unroll
        for (int n = 0; n < 8; n++) acc[m][n] = 0ull;

    ldg(0); sts(0); __syncthreads();

    for (int tt = 0; tt < T; tt++){
        const int cur = tt & 1;
        if (tt + 1 < T) ldg(tt + 1);
        #pragma unroll
        for (int k = 0; k < 16; k++){
            // A: m-pairs ty*8..ty*8+7 as two aligned 16B reads (float indices)
            ulonglong2 A01 = *(const ulonglong2*)&As[cur][k][ty*8];
            ulonglong2 A23 = *(const ulonglong2*)&As[cur][k][ty*8 + 4];
            float4 bq0 = *(const float4*)&Bs[cur][k][tx*4];        // cols tx*8..+3
            float4 bq1 = *(const float4*)&Bs[cur][k][64 + tx*4];   // cols tx*8+4..+7
            u64 av[4] = {A01.x, A01.y, A23.x, A23.y};
            u64 bd[8] = {pack2(bq0.x,bq0.x), pack2(bq0.y,bq0.y),
                         pack2(bq0.z,bq0.z), pack2(bq0.w,bq0.w),
                         pack2(bq1.x,bq1.x), pack2(bq1.y,bq1.y),
                         pack2(bq1.z,bq1.z), pack2(bq1.w,bq1.w)};
            #pragma unroll
            for (int m = 0; m < 4; m++)
                #pragma unroll
                for (int n = 0; n < 8; n++)
                    acc[m][n] = fma2(av[m], bd[n], acc[m][n]);
        }
        if (tt + 1 < T) sts(cur ^ 1);
        __syncthreads();
    }

    const float alpha = (MODE == 2) ? alpha_p[0] : 1.0f;
    const int nbase = n0 + tx*8;
    float badd[8];
    if (MODE == 2){
        float4 v0 = *(const float4*)(bias2 + nbase);
        float4 v1 = *(const float4*)(bias2 + nbase + 4);
        badd[0]=v0.x; badd[1]=v0.y; badd[2]=v0.z; badd[3]=v0.w;
        badd[4]=v1.x; badd[5]=v1.y; badd[6]=v1.z; badd[7]=v1.w;
    }
    #pragma unroll
    for (int r = 0; r < 8; r++){
        const int mp = r >> 1, part = r & 1;
        float out[8];
        #pragma unroll
        for (int q = 0; q < 8; q++){
            float2 v = unpack2(acc[mp][q]);
            out[q] = part ? v.y : v.x;
        }
        if (MODE == 2){
            #pragma unroll
            for (int q = 0; q < 8; q++) out[q] = (out[q] + badd[q]) * alpha;
        }
        float* dst;
        const size_t roff = (size_t)(rowbase + ty*8 + r)*Hn + nbase;
        if      (MODE == 0) dst = (ks == 0 ? g_ctxA : g_ctxB) + roff;
        else if (MODE == 1) dst = (ks == 0 ? g_h1A  : g_h1B ) + roff;
        else                dst = Cout + roff;
        *(float4*)dst       = *(float4*)&out[0];
        *(float4*)(dst + 4) = *(float4*)&out[4];
    }
}

// =============================== launch ===============================
extern "C" void kernel_launch(void* const* d_in, const int* in_sizes, int n_in,
                              void* d_out, int out_size)
{
    const float* Hj    = (const float*)d_in[0];
    const float* Hi    = (const float*)d_in[1];
    const float* mask  = (const float*)d_in[2];
    const float* Wpj   = (const float*)d_in[3];
    const float* Wpi   = (const float*)d_in[4];
    const float* Ws1   = (const float*)d_in[5];
    const float* bs1   = (const float*)d_in[6];
    const float* Ws2   = (const float*)d_in[7];
    const float* bs2   = (const float*)d_in[8];
    const float* Wv1   = (const float*)d_in[9];
    const float* bv1   = (const float*)d_in[10];
    const float* Wv2   = (const float*)d_in[11];
    const float* bv2   = (const float*)d_in[12];
    const float* alpha = (const float*)d_in[13];
    float* out = (float*)d_out;

    k_proj<<<Bn*Sn, 256>>>(Hj, Hi, Wpj, Wpi, Ws1, bs1);

    dim3 gp(Sn/32, Sn/16, Bn);
    k_pair<<<gp, 256>>>(Ws1, Ws2, bs2);

    k_softmax<<<Bn*Sn, 256>>>(mask);

    dim3 g0(Hn/128, Sn/64, Bn*2);
    k_gemm<0><<<g0, 128>>>(Hi, nullptr, nullptr, nullptr, nullptr, nullptr);

    dim3 g1(Hn/128, (Bn*Sn)/64, 2);
    k_gemm<1><<<g1, 128>>>(Wv1, Hj, nullptr, nullptr, nullptr, nullptr);

    dim3 g2(Hn/128, (Bn*Sn)/64, 1);
    k_gemm<2><<<g2, 128>>>(Wv2, nullptr, bv1, bv2, alpha, out);
}

// round 8
// speedup vs baseline: 2.3569x; 1.3256x over previous
#include <cuda_runtime.h>
#include <cuda_bf16.h>

typedef unsigned long long u64;
typedef unsigned int u32;

#define Bn   2
#define Sn   1024
#define Hn   768
#define Dn   24
#define HIDn 96

// ---------------- scratch ----------------
__device__ float g_Zj  [Bn*Sn*Dn];
__device__ float g_Zi  [Bn*Sn*Dn];
__device__ float g_Cj  [Bn*Sn*HIDn];
__device__ float g_Ci  [Bn*Sn*HIDn];
__device__ float g_P   [Bn*Sn*Sn];
__device__ float g_ctxA[Bn*Sn*Hn];
__device__ float g_ctxB[Bn*Sn*Hn];
__device__ float g_h1A [Bn*Sn*Hn];
__device__ float g_h1B [Bn*Sn*Hn];

// ---------------- packed f32x2 helpers ----------------
__device__ __forceinline__ u64 pack2(float x, float y){
    u64 r;
    asm("mov.b64 %0, {%1, %2};" : "=l"(r)
        : "r"(__float_as_uint(x)), "r"(__float_as_uint(y)));
    return r;
}
__device__ __forceinline__ float2 unpack2(u64 v){
    unsigned lo, hi;
    asm("mov.b64 {%0, %1}, %2;" : "=r"(lo), "=r"(hi) : "l"(v));
    return make_float2(__uint_as_float(lo), __uint_as_float(hi));
}
__device__ __forceinline__ u64 fma2(u64 a, u64 b, u64 c){
    u64 d;
    asm("fma.rn.f32x2 %0, %1, %2, %3;" : "=l"(d) : "l"(a), "l"(b), "l"(c));
    return d;
}
__device__ __forceinline__ int swzB(int n){
    return ((n >> 2) & 1) * 64 + ((n >> 3) << 2) + (n & 3);
}
__device__ __forceinline__ u32 f2tf32(float f){
    u32 r;
    asm("cvt.rna.tf32.f32 %0, %1;" : "=r"(r) : "f"(f));
    return r;
}
__device__ __forceinline__ void mma_tf32(
    float& d0, float& d1, float& d2, float& d3,
    u32 a0, u32 a1, u32 a2, u32 a3, u32 b0, u32 b1)
{
    asm("mma.sync.aligned.m16n8k8.row.col.f32.tf32.tf32.f32 "
        "{%0,%1,%2,%3},{%4,%5,%6,%7},{%8,%9},{%0,%1,%2,%3};"
        : "+f"(d0), "+f"(d1), "+f"(d2), "+f"(d3)
        : "r"(a0), "r"(a1), "r"(a2), "r"(a3), "r"(b0), "r"(b1));
}

// =================== kernel 1: projections + per-token MLP terms ===================
__global__ __launch_bounds__(256) void k_proj(
    const float* __restrict__ Hj, const float* __restrict__ Hi,
    const float* __restrict__ Wpj, const float* __restrict__ Wpi,
    const float* __restrict__ Ws1, const float* __restrict__ bs1)
{
    __shared__ float shj[Hn], shi[Hn];
    __shared__ float sz[48];
    __shared__ float sws1[96][97];
    const int row = blockIdx.x;
    const int t = threadIdx.x;
    const float* hj = Hj + (size_t)row*Hn;
    const float* hi = Hi + (size_t)row*Hn;
    for (int k = t; k < Hn; k += 256){ shj[k] = hj[k]; shi[k] = hi[k]; }
    for (int idx = t; idx < 96*96; idx += 256) sws1[idx/96][idx%96] = Ws1[idx];
    __syncthreads();

    const int w = t >> 5, lane = t & 31;
    for (int o = w; o < 48; o += 8){
        const float* wv = (o < 24) ? (Wpj + (size_t)o*Hn) : (Wpi + (size_t)(o-24)*Hn);
        const float* x  = (o < 24) ? shj : shi;
        float s0 = 0.f, s1 = 0.f;
        #pragma unroll
        for (int h = lane; h < Hn; h += 64){
            s0 = fmaf(wv[h],    x[h],    s0);
            s1 = fmaf(wv[h+32], x[h+32], s1);
        }
        float s = s0 + s1;
        #pragma unroll
        for (int off = 16; off; off >>= 1) s += __shfl_xor_sync(0xffffffffu, s, off);
        if (lane == 0){
            sz[o] = s;
            if (o < 24) g_Zj[(size_t)row*24 + o]      = s;
            else        g_Zi[(size_t)row*24 + (o-24)] = s;
        }
    }
    __syncthreads();

    if (t < 192){
        int h = (t < 96) ? t : t - 96;
        const float* z  = (t < 96) ? sz : (sz + 24);
        const float* wr = &sws1[h][(t < 96) ? 0 : 24];
        float s = (t < 96) ? 0.f : bs1[h];
        #pragma unroll
        for (int d = 0; d < 24; d++) s = fmaf(wr[d], z[d], s);
        if (t < 96) g_Cj[(size_t)row*96 + h] = s;
        else        g_Ci[(size_t)row*96 + h] = s;
    }
}

// =================== kernel 2: pair MLP via tf32 mma.sync ===================
// CTA: 256 thr = 8 warps. Owns i-tile of 128 (blockIdx.x) and loops over a
// 128-j chunk (blockIdx.y), batch = blockIdx.z. Warp w owns i-cols w*16..+15.
// Per j: logits[j, i0..i0+127] = bs2 + sum_h ws2[h]*relu( (W1dyn@F_j)[h,i]
//                                                         + Cj[j,h] + Ci[i,h] )
// W1dyn = Ws1[:,48:96] (tf32, frag-swizzled, loaded once).
// F_j[k,i] (48 x 128) built per j into frag layout, double-buffered.
#define JT 128
#define IT 128

// dynamic smem layout (bytes):
#define OFF_ASW  0                          // 1152 uint4  = 18432
#define OFF_BSW  18432                      // 2*3072 uint2 = 49152
#define OFF_CI   (18432+49152)              // 128*100 f   = 51200
#define OFF_ZI   (OFF_CI+51200)             // 128*25  f   = 12800
#define OFF_ZJ   (OFF_ZI+12800)             // 128*25  f   = 12800
#define OFF_CJ   (OFF_ZJ+12800)             // 2*96    f   = 768
#define SMEM_PAIR (OFF_CJ+768)

__global__ __launch_bounds__(256) void k_pair_mma(
    const float* __restrict__ Ws1, const float* __restrict__ Ws2,
    const float* __restrict__ bs2)
{
    extern __shared__ __align__(16) char smem[];
    uint4* Asw  = (uint4*)(smem + OFF_ASW);      // [mt][kt][lane]
    uint2* Bsw  = (uint2*)(smem + OFF_BSW);      // [p][kt][w][nt][lane]
    float* Ci_s = (float*)(smem + OFF_CI);       // [i][100]
    float* Zi_s = (float*)(smem + OFF_ZI);       // [i][25]
    float* Zj_s = (float*)(smem + OFF_ZJ);       // [j][25]
    float* Cj_s = (float*)(smem + OFF_CJ);       // [p][96]

    const int t  = threadIdx.x;
    const int i0 = blockIdx.x * IT;
    const int j0 = blockIdx.y * JT;
    const int b  = blockIdx.z;
    const int base = b * Sn;
    const int w = t >> 5, lane = t & 31;
    const int g = lane >> 2, t4 = lane & 3;

    // ---- static loads ----
    for (int idx = t; idx < 1152; idx += 256){     // A frag swizzle (W1dyn tf32)
        int mt = idx / 192, r = idx % 192, kt = r / 32, ln = r % 32;
        int gg = ln >> 2, tt = ln & 3;
        int h = mt*16 + gg, k = kt*8 + tt;
        uint4 v;
        v.x = f2tf32(Ws1[h*96 + 48 + k]);
        v.y = f2tf32(Ws1[(h+8)*96 + 48 + k]);
        v.z = f2tf32(Ws1[h*96 + 48 + k + 4]);
        v.w = f2tf32(Ws1[(h+8)*96 + 48 + k + 4]);
        Asw[idx] = v;
    }
    for (int idx = t; idx < IT*96; idx += 256){
        int r = idx / 96, h = idx % 96;
        Ci_s[r*100 + h] = g_Ci[(size_t)(base + i0 + r)*96 + h];
    }
    for (int idx = t; idx < IT*24; idx += 256){
        int r = idx / 24, k = idx % 24;
        Zi_s[r*25 + k] = g_Zi[(size_t)(base + i0 + r)*24 + k];
    }
    for (int idx = t; idx < JT*24; idx += 256){
        int r = idx / 24, k = idx % 24;
        Zj_s[r*25 + k] = g_Zj[(size_t)(base + j0 + r)*24 + k];
    }
    const float bs2v = bs2[0];
    float ws[6][2];
    #pragma unroll
    for (int mt = 0; mt < 6; mt++){
        ws[mt][0] = Ws2[mt*16 + g];
        ws[mt][1] = Ws2[mt*16 + g + 8];
    }
    __syncthreads();

    // feature builder: fills Bsw[p] + Cj_s[p] for row jn
    auto build = [&](int jn, int p){
        if (t < 96) Cj_s[p*96 + t] = g_Cj[(size_t)(base + j0 + jn)*96 + t];
        const float* zj = &Zj_s[jn*25];
        uint2* dst = Bsw + p*3072;
        #pragma unroll
        for (int q = 0; q < 12; q++){
            int e = t + q*256;
            int kt = e >> 9, ww = (e >> 6) & 7, nt = (e >> 5) & 1, ln = e & 31;
            int gg = ln >> 2, tt = ln & 3;
            int col = ww*16 + nt*8 + gg;
            int k0 = kt*8 + tt, k1 = k0 + 4;
            const float* zi = &Zi_s[col*25];
            float f0, f1;
            if (kt < 3){ f0 = zj[k0]*zi[k0]; f1 = zj[k1]*zi[k1]; }
            else { f0 = fabsf(zj[k0-24] - zi[k0-24]); f1 = fabsf(zj[k1-24] - zi[k1-24]); }
            uint2 u; u.x = f2tf32(f0); u.y = f2tf32(f1);
            dst[e] = u;
        }
    };

    build(0, 0);
    __syncthreads();

    const int ccol = w*16 + 2*t4;   // this thread's col for nt=0 (Ci index base)

    for (int jj = 0; jj < JT; jj++){
        const int p = jj & 1;
        if (jj + 1 < JT) build(jj + 1, p ^ 1);

        // Cj for this j (frag h-pattern)
        float cj[6][2];
        #pragma unroll
        for (int mt = 0; mt < 6; mt++){
            cj[mt][0] = Cj_s[p*96 + mt*16 + g];
            cj[mt][1] = Cj_s[p*96 + mt*16 + g + 8];
        }
        // B frags (this warp's 16 cols)
        u32 bf[2][6][2];
        #pragma unroll
        for (int nt = 0; nt < 2; nt++)
            #pragma unroll
            for (int kt = 0; kt < 6; kt++){
                uint2 u = Bsw[p*3072 + ((kt*8 + w)*2 + nt)*32 + lane];
                bf[nt][kt][0] = u.x; bf[nt][kt][1] = u.y;
            }

        float pA[4] = {0.f, 0.f, 0.f, 0.f};
        #pragma unroll
        for (int mt = 0; mt < 6; mt++){
            uint4 af[6];
            #pragma unroll
            for (int kt = 0; kt < 6; kt++) af[kt] = Asw[(mt*6 + kt)*32 + lane];
            #pragma unroll
            for (int nt = 0; nt < 2; nt++){
                float d0 = 0.f, d1 = 0.f, d2 = 0.f, d3 = 0.f;
                #pragma unroll
                for (int kt = 0; kt < 6; kt++)
                    mma_tf32(d0, d1, d2, d3,
                             af[kt].x, af[kt].y, af[kt].z, af[kt].w,
                             bf[nt][kt][0], bf[nt][kt][1]);
                const int c = ccol + nt*8;
                const int h0 = mt*16 + g;
                float v0 = fmaxf(d0 + cj[mt][0] + Ci_s[c*100 + h0],        0.f);
                float v1 = fmaxf(d1 + cj[mt][0] + Ci_s[(c+1)*100 + h0],    0.f);
                float v2 = fmaxf(d2 + cj[mt][1] + Ci_s[c*100 + h0 + 8],    0.f);
                float v3 = fmaxf(d3 + cj[mt][1] + Ci_s[(c+1)*100 + h0 + 8],0.f);
                pA[nt*2]   = fmaf(ws[mt][0], v0, fmaf(ws[mt][1], v2, pA[nt*2]));
                pA[nt*2+1] = fmaf(ws[mt][0], v1, fmaf(ws[mt][1], v3, pA[nt*2+1]));
            }
        }
        // reduce over g (lanes differing in bits 2..4)
        #pragma unroll
        for (int q = 0; q < 4; q++){
            pA[q] += __shfl_xor_sync(0xffffffffu, pA[q], 4);
            pA[q] += __shfl_xor_sync(0xffffffffu, pA[q], 8);
            pA[q] += __shfl_xor_sync(0xffffffffu, pA[q], 16);
        }
        if (g == 0){
            float* dst = &g_P[(size_t)(base + j0 + jj)*Sn + i0 + w*16];
            *(float2*)(dst + 2*t4)     = make_float2(pA[0] + bs2v, pA[1] + bs2v);
            *(float2*)(dst + 8 + 2*t4) = make_float2(pA[2] + bs2v, pA[3] + bs2v);
        }
        __syncthreads();
    }
}

// =================== kernel 3: masked softmax over i (in place) ===================
__global__ __launch_bounds__(256) void k_softmax(const float* __restrict__ mask){
    const int r = blockIdx.x;
    const int b = r / Sn;
    float* row = g_P + (size_t)r*Sn;
    const float* mrow = mask + (size_t)b*Sn;
    const int t = threadIdx.x;
    __shared__ float red[256];

    float vals[4]; float mx = -3.402823466e38f;
    #pragma unroll
    for (int q = 0; q < 4; q++){
        int i = t + q*256;
        float v = row[i] + (1.0f - mrow[i]) * (-3.402823466e38f);
        vals[q] = v; mx = fmaxf(mx, v);
    }
    red[t] = mx; __syncthreads();
    for (int s = 128; s > 0; s >>= 1){ if (t < s) red[t] = fmaxf(red[t], red[t+s]); __syncthreads(); }
    mx = red[0]; __syncthreads();

    float sum = 0.f;
    #pragma unroll
    for (int q = 0; q < 4; q++){ vals[q] = __expf(vals[q] - mx); sum += vals[q]; }
    red[t] = sum; __syncthreads();
    for (int s = 128; s > 0; s >>= 1){ if (t < s) red[t] += red[t+s]; __syncthreads(); }
    float inv = 1.0f / red[0];
    #pragma unroll
    for (int q = 0; q < 4; q++) row[t + q*256] = vals[q] * inv;
}

// =================== balanced f32x2 GEMM (unchanged from R6 pass) ===================
template<int MODE>
__global__ __launch_bounds__(128) void k_gemm(
    const float* __restrict__ BW,
    const float* __restrict__ Hj,
    const float* __restrict__ bias,
    const float* __restrict__ bias2,
    const float* __restrict__ alpha_p,
    float* __restrict__ Cout)
{
    constexpr int KH = (MODE == 0) ? 512 : (MODE == 1) ? 1152 : 768;
    constexpr int T  = KH / 16;
    __shared__ __align__(16) float As[2][16][64];
    __shared__ __align__(16) float Bs[2][16][128];

    const int t  = threadIdx.x;
    const int n0 = blockIdx.x * 128;
    const int m0 = blockIdx.y * 64;
    int b = 0, ks = 0;
    if (MODE == 0){ b = blockIdx.z >> 1; ks = blockIdx.z & 1; }
    if (MODE == 1){ ks = blockIdx.z; }
    const int rowbase = (MODE == 0) ? b*Sn + m0 : m0;
    const int kbase   = ks * KH;

    const int am = t >> 1, ah8 = (t & 1) * 8;
    const int b0r = t >> 3, b0q = (t & 7);
    const int ty = t >> 4, tx = t & 15;
    const int swt = swzB(t & 127);

    const float* ArowP  = g_P    + (size_t)(rowbase + am)*Sn + kbase;
    const float* ArowCA = g_ctxA + (size_t)(rowbase + am)*Hn;
    const float* ArowCB = g_ctxB + (size_t)(rowbase + am)*Hn;
    const float* ArowH  = (MODE == 1) ? (Hj + (size_t)(rowbase + am)*Hn) : (const float*)0;
    const float* ArowA  = g_h1A  + (size_t)(rowbase + am)*Hn;
    const float* ArowB  = g_h1B  + (size_t)(rowbase + am)*Hn;
    const float* Bsrc   = (MODE == 0) ? (BW + (size_t)b*Sn*Hn) : BW;

    float4 ra0, ra1, rb0, rb1, rb2, rb3;

    auto ldg = [&](int kt){
        const int kb = kt * 16;
        if (MODE == 0){
            ra0 = *(const float4*)(ArowP + kb + ah8);
            ra1 = *(const float4*)(ArowP + kb + ah8 + 4);
        } else if (MODE == 2){
            const int fo = kb + ah8;
            float4 xa0 = *(const float4*)(ArowA + fo);
            float4 xa1 = *(const float4*)(ArowA + fo + 4);
            float4 xb0 = *(const float4*)(ArowB + fo);
            float4 xb1 = *(const float4*)(ArowB + fo + 4);
            float4 bb0 = *(const float4*)(bias + fo);
            float4 bb1 = *(const float4*)(bias + fo + 4);
            ra0 = make_float4(fmaxf(xa0.x+xb0.x+bb0.x,0.f), fmaxf(xa0.y+xb0.y+bb0.y,0.f),
                              fmaxf(xa0.z+xb0.z+bb0.z,0.f), fmaxf(xa0.w+xb0.w+bb0.w,0.f));
            ra1 = make_float4(fmaxf(xa1.x+xb1.x+bb1.x,0.f), fmaxf(xa1.y+xb1.y+bb1.y,0.f),
                              fmaxf(xa1.z+xb1.z+bb1.z,0.f), fmaxf(xa1.w+xb1.w+bb1.w,0.f));
        } else {
            const int fo = kbase + kb + ah8;
            if (fo < 768){
                float4 c0 = *(const float4*)(ArowCA + fo);
                float4 c1 = *(const float4*)(ArowCA + fo + 4);
                float4 d0 = *(const float4*)(ArowCB + fo);
                float4 d1 = *(const float4*)(ArowCB + fo + 4);
                ra0 = make_float4(c0.x+d0.x, c0.y+d0.y, c0.z+d0.z, c0.w+d0.w);
                ra1 = make_float4(c1.x+d1.x, c1.y+d1.y, c1.z+d1.z, c1.w+d1.w);
            } else if (fo < 1536){
                ra0 = *(const float4*)(ArowH + fo - 768);
                ra1 = *(const float4*)(ArowH + fo - 764);
            } else {
                const int go = fo - 1536;
                float4 c0 = *(const float4*)(ArowCA + go);
                float4 c1 = *(const float4*)(ArowCA + go + 4);
                float4 d0 = *(const float4*)(ArowCB + go);
                float4 d1 = *(const float4*)(ArowCB + go + 4);
                float4 h0 = *(const float4*)(ArowH + go);
                float4 h1 = *(const float4*)(ArowH + go + 4);
                ra0 = make_float4((c0.x+d0.x)*h0.x, (c0.y+d0.y)*h0.y,
                                  (c0.z+d0.z)*h0.z, (c0.w+d0.w)*h0.w);
                ra1 = make_float4((c1.x+d1.x)*h1.x, (c1.y+d1.y)*h1.y,
                                  (c1.z+d1.z)*h1.z, (c1.w+d1.w)*h1.w);
            }
        }
        if (MODE == 0){
            const float* s = Bsrc + (size_t)(kbase + kb + b0r)*Hn + n0 + b0q*16;
            rb0 = *(const float4*)s;       rb1 = *(const float4*)(s + 4);
            rb2 = *(const float4*)(s + 8); rb3 = *(const float4*)(s + 12);
        } else {
            constexpr int KW = (MODE == 1) ? 2304 : 768;
            const float* s = Bsrc + (size_t)(n0 + t)*KW + kbase + kb;
            rb0 = *(const float4*)s;       rb1 = *(const float4*)(s + 4);
            rb2 = *(const float4*)(s + 8); rb3 = *(const float4*)(s + 12);
        }
    };
    auto sts = [&](int buf){
        float* Af = &As[buf][0][0];
        Af[(ah8+0)*64 + am] = ra0.x; Af[(ah8+1)*64 + am] = ra0.y;
        Af[(ah8+2)*64 + am] = ra0.z; Af[(ah8+3)*64 + am] = ra0.w;
        Af[(ah8+4)*64 + am] = ra1.x; Af[(ah8+5)*64 + am] = ra1.y;
        Af[(ah8+6)*64 + am] = ra1.z; Af[(ah8+7)*64 + am] = ra1.w;
        if (MODE == 0){
            float* d = &Bs[buf][b0r][0];
            *(float4*)(d + 8*b0q)          = rb0;
            *(float4*)(d + 64 + 8*b0q)     = rb1;
            *(float4*)(d + 8*b0q + 4)      = rb2;
            *(float4*)(d + 64 + 8*b0q + 4) = rb3;
        } else {
            Bs[buf][ 0][swt] = rb0.x; Bs[buf][ 1][swt] = rb0.y;
            Bs[buf][ 2][swt] = rb0.z; Bs[buf][ 3][swt] = rb0.w;
            Bs[buf][ 4][swt] = rb1.x; Bs[buf][ 5][swt] = rb1.y;
            Bs[buf][ 6][swt] = rb1.z; Bs[buf][ 7][swt] = rb1.w;
            Bs[buf][ 8][swt] = rb2.x; Bs[buf][ 9][swt] = rb2.y;
            Bs[buf][10][swt] = rb2.z; Bs[buf][11][swt] = rb2.w;
            Bs[buf][12][swt] = rb3.x; Bs[buf][13][swt] = rb3.y;
            Bs[buf][14][swt] = rb3.z; Bs[buf][15][swt] = rb3.w;
        }
    };

    u64 acc[4][8];
    #pragma unroll
    for (int m = 0; m < 4; m++)
        #pragma unroll
        for (int n = 0; n < 8; n++) acc[m][n] = 0ull;

    ldg(0); sts(0); __syncthreads();

    for (int tt = 0; tt < T; tt++){
        const int cur = tt & 1;
        if (tt + 1 < T) ldg(tt + 1);
        #pragma unroll
        for (int k = 0; k < 16; k++){
            ulonglong2 A01 = *(const ulonglong2*)&As[cur][k][ty*8];
            ulonglong2 A23 = *(const ulonglong2*)&As[cur][k][ty*8 + 4];
            float4 bq0 = *(const float4*)&Bs[cur][k][tx*4];
            float4 bq1 = *(const float4*)&Bs[cur][k][64 + tx*4];
            u64 av[4] = {A01.x, A01.y, A23.x, A23.y};
            u64 bd[8] = {pack2(bq0.x,bq0.x), pack2(bq0.y,bq0.y),
                         pack2(bq0.z,bq0.z), pack2(bq0.w,bq0.w),
                         pack2(bq1.x,bq1.x), pack2(bq1.y,bq1.y),
                         pack2(bq1.z,bq1.z), pack2(bq1.w,bq1.w)};
            #pragma unroll
            for (int m = 0; m < 4; m++)
                #pragma unroll
                for (int n = 0; n < 8; n++)
                    acc[m][n] = fma2(av[m], bd[n], acc[m][n]);
        }
        if (tt + 1 < T) sts(cur ^ 1);
        __syncthreads();
    }

    const float alpha = (MODE == 2) ? alpha_p[0] : 1.0f;
    const int nbase = n0 + tx*8;
    float badd[8];
    if (MODE == 2){
        float4 v0 = *(const float4*)(bias2 + nbase);
        float4 v1 = *(const float4*)(bias2 + nbase + 4);
        badd[0]=v0.x; badd[1]=v0.y; badd[2]=v0.z; badd[3]=v0.w;
        badd[4]=v1.x; badd[5]=v1.y; badd[6]=v1.z; badd[7]=v1.w;
    }
    #pragma unroll
    for (int r = 0; r < 8; r++){
        const int mp = r >> 1, part = r & 1;
        float out[8];
        #pragma unroll
        for (int q = 0; q < 8; q++){
            float2 v = unpack2(acc[mp][q]);
            out[q] = part ? v.y : v.x;
        }
        if (MODE == 2){
            #pragma unroll
            for (int q = 0; q < 8; q++) out[q] = (out[q] + badd[q]) * alpha;
        }
        float* dst;
        const size_t roff = (size_t)(rowbase + ty*8 + r)*Hn + nbase;
        if      (MODE == 0) dst = (ks == 0 ? g_ctxA : g_ctxB) + roff;
        else if (MODE == 1) dst = (ks == 0 ? g_h1A  : g_h1B ) + roff;
        else                dst = Cout + roff;
        *(float4*)dst       = *(float4*)&out[0];
        *(float4*)(dst + 4) = *(float4*)&out[4];
    }
}

// =============================== launch ===============================
extern "C" void kernel_launch(void* const* d_in, const int* in_sizes, int n_in,
                              void* d_out, int out_size)
{
    const float* Hj    = (const float*)d_in[0];
    const float* Hi    = (const float*)d_in[1];
    const float* mask  = (const float*)d_in[2];
    const float* Wpj   = (const float*)d_in[3];
    const float* Wpi   = (const float*)d_in[4];
    const float* Ws1   = (const float*)d_in[5];
    const float* bs1   = (const float*)d_in[6];
    const float* Ws2   = (const float*)d_in[7];
    const float* bs2   = (const float*)d_in[8];
    const float* Wv1   = (const float*)d_in[9];
    const float* bv1   = (const float*)d_in[10];
    const float* Wv2   = (const float*)d_in[11];
    const float* bv2   = (const float*)d_in[12];
    const float* alpha = (const float*)d_in[13];
    float* out = (float*)d_out;

    cudaFuncSetAttribute(k_pair_mma, cudaFuncAttributeMaxDynamicSharedMemorySize, SMEM_PAIR);

    k_proj<<<Bn*Sn, 256>>>(Hj, Hi, Wpj, Wpi, Ws1, bs1);

    dim3 gp(Sn/IT, Sn/JT, Bn);
    k_pair_mma<<<gp, 256, SMEM_PAIR>>>(Ws1, Ws2, bs2);

    k_softmax<<<Bn*Sn, 256>>>(mask);

    dim3 g0(Hn/128, Sn/64, Bn*2);
    k_gemm<0><<<g0, 128>>>(Hi, nullptr, nullptr, nullptr, nullptr, nullptr);

    dim3 g1(Hn/128, (Bn*Sn)/64, 2);
    k_gemm<1><<<g1, 128>>>(Wv1, Hj, nullptr, nullptr, nullptr, nullptr);

    dim3 g2(Hn/128, (Bn*Sn)/64, 1);
    k_gemm<2><<<g2, 128>>>(Wv2, nullptr, bv1, bv2, alpha, out);
}